// round 11
// baseline (speedup 1.0000x reference)
#include <cuda_runtime.h>
#include <cuda_fp16.h>
#include <math.h>
#include <stdint.h>

// ---------------------------------------------------------------------------
// GCGRU encoder-decoder. FP16 legacy tensor cores (mma.m16n8k16, fp32 accum),
// ldmatrix fragment loads, 2-stage cp.async double buffering.
// R11: 4-warp CTAs with 64x64 warp tiles (halved ldmatrix bytes/FLOP).
//
// Layouts (all half):
//   g_X*  : (N, din_p, B)        stage-1 input, pad cols zero
//   g_Y*  : (slot, N, din_p, B)  stage-1 output for supports {1,2,4,5};
//                                identity supports (0,3) read from g_X.
//   g_Gt  : (slot, N, N)         4 non-identity supports
//   g_Wp  : padded (K*din_p, outd) weights
// ---------------------------------------------------------------------------

#define N_    1024
#define B_    64
#define T_    12
#define HOR_  12
#define C_    2
#define H_    64
#define K_    6

#define NBH_  (N_ * B_ * H_)
#define M_    (N_ * B_)

#define DINR0 66
#define DINP0 80
#define DINR1 128
#define DINP1 128

// ------------------------- scratch (device globals) -------------------------
__device__ float  g_xT[T_ * N_ * B_ * C_];
__device__ float  g_seq[T_ * N_ * B_ * H_];
__device__ float  g_hA[NBH_];
__device__ float  g_hB[NBH_];
__device__ __half g_X0[N_ * DINP0 * B_];
__device__ __half g_X1[N_ * DINP1 * B_];
__device__ __half g_Y0[4ll * N_ * DINP0 * B_];
__device__ __half g_Y1[4ll * N_ * DINP1 * B_];
__device__ float  g_zr[(size_t)M_ * 2 * H_];
__device__ float  g_y[M_ * C_];
__device__ __half g_Gt[4 * N_ * N_];
__device__ __half g_Wp[479232];

// ------------------------------ helpers -------------------------------------
__device__ __forceinline__ void mma_f16(float* c, const uint32_t* a,
                                        const uint32_t* b) {
    asm volatile(
        "mma.sync.aligned.m16n8k16.row.col.f32.f16.f16.f32 "
        "{%0,%1,%2,%3}, {%4,%5,%6,%7}, {%8,%9}, {%0,%1,%2,%3};\n"
        : "+f"(c[0]), "+f"(c[1]), "+f"(c[2]), "+f"(c[3])
        : "r"(a[0]), "r"(a[1]), "r"(a[2]), "r"(a[3]), "r"(b[0]), "r"(b[1]));
}

__device__ __forceinline__ void ldmx4(uint32_t* r, const void* p) {
    uint32_t a = (uint32_t)__cvta_generic_to_shared(p);
    asm volatile("ldmatrix.sync.aligned.m8n8.x4.shared.b16 {%0,%1,%2,%3}, [%4];"
                 : "=r"(r[0]), "=r"(r[1]), "=r"(r[2]), "=r"(r[3]) : "r"(a));
}
__device__ __forceinline__ void ldmx4t(uint32_t* r, const void* p) {
    uint32_t a = (uint32_t)__cvta_generic_to_shared(p);
    asm volatile("ldmatrix.sync.aligned.m8n8.x4.trans.shared.b16 {%0,%1,%2,%3}, [%4];"
                 : "=r"(r[0]), "=r"(r[1]), "=r"(r[2]), "=r"(r[3]) : "r"(a));
}

__device__ __forceinline__ void cp16(void* dst, const void* src) {
    uint32_t d = (uint32_t)__cvta_generic_to_shared(dst);
    asm volatile("cp.async.ca.shared.global [%0], [%1], 16;\n"
                 :: "r"(d), "l"(src));
}
__device__ __forceinline__ void cp16cg(void* dst, const void* src) {
    uint32_t d = (uint32_t)__cvta_generic_to_shared(dst);
    asm volatile("cp.async.cg.shared.global [%0], [%1], 16;\n"
                 :: "r"(d), "l"(src));
}
__device__ __forceinline__ void cp_commit() {
    asm volatile("cp.async.commit_group;\n");
}
template <int n>
__device__ __forceinline__ void cp_wait() {
    asm volatile("cp.async.wait_group %0;\n" :: "n"(n));
}

// ------------------------------ prep kernels --------------------------------

__global__ void k_prep_G(const float* __restrict__ G) {
    int idx = blockIdx.x * blockDim.x + threadIdx.x;
    if (idx >= 4 * N_ * N_) return;
    int s = idx / (N_ * N_);
    int r = idx - s * (N_ * N_);
    int kidx = s + 1 + (s >> 1);   // {1,2,4,5}
    g_Gt[idx] = __float2half_rn(G[(size_t)kidx * N_ * N_ + r]);
}

__global__ void k_prep_W(const float* __restrict__ src, __half* __restrict__ dst,
                         int din_r, int din_p, int outd) {
    int idx = blockIdx.x * blockDim.x + threadIdx.x;
    int total = K_ * din_p * outd;
    if (idx >= total) return;
    int o = idx % outd;
    int row = idx / outd;
    int k = row / din_p;
    int f = row - k * din_p;
    dst[idx] = (f < din_r) ? __float2half_rn(src[(size_t)(k * din_r + f) * outd + o])
                           : __float2half_rn(0.f);
}

// ------------------------------ data movement -------------------------------

// x (B,T,N,C) -> g_xT (T,N,B,C)
__global__ void k_transpose_x(const float* __restrict__ x) {
    int idx = blockIdx.x * blockDim.x + threadIdx.x;
    const int total = B_ * T_ * N_ * C_;
    if (idx >= total) return;
    int c = idx % C_;
    int i = (idx / C_) % N_;
    int t = (idx / (C_ * N_)) % T_;
    int b = idx / (C_ * N_ * T_);
    g_xT[(((size_t)t * N_ + i) * B_ + b) * C_ + c] = x[idx];
}

// Gate-pass concat: X[i][f][b] = concat(x,h), f < din_r, fp16-rounded.
__global__ void k_concat_full(const float* __restrict__ xin, int dinx,
                              const float* __restrict__ h,
                              __half* __restrict__ X, int din_r, int din_p) {
    int idx = blockIdx.x * blockDim.x + threadIdx.x;
    int total = N_ * din_r * B_;
    if (idx >= total) return;
    int b = idx & 63;
    int f = (idx >> 6) % din_r;
    int i = idx / (64 * din_r);
    int m = i * B_ + b;
    float v;
    if (f < dinx) v = xin[(size_t)m * dinx + f];
    else          v = h ? h[(size_t)m * H_ + (f - dinx)] : 0.f;
    X[((size_t)i * din_p + f) * B_ + b] = __float2half_rn(v);
}

// Candidate-pass concat: overwrite h-part with r*h.
__global__ void k_concat_h(const float* __restrict__ h, int dinx,
                           __half* __restrict__ X, int din_p) {
    int idx = blockIdx.x * blockDim.x + threadIdx.x;
    int total = N_ * H_ * B_;
    if (idx >= total) return;
    int b = idx & 63;
    int j = (idx >> 6) & 63;
    int i = idx >> 12;
    int m = i * B_ + b;
    float v = 0.f;
    if (h) v = h[(size_t)m * H_ + j] * g_zr[(size_t)m * (2 * H_) + H_ + j];
    X[((size_t)i * din_p + (dinx + j)) * B_ + b] = __float2half_rn(v);
}

// ------------------------------ stage-1 GEMM --------------------------------
// Y[s] = G[s] @ X over columns [col_off, col_off + gridX*128).
// BM=128, BN=128, BK=64, 4 warps (2x2), warp tile 64x64, fp16 mma m16n8k16.
// 2-stage cp.async double buffering in dynamic smem; 16 K-iterations.
#define G1_A_ROWS 128
#define G1_A_LD   72
#define G1_B_ROWS 64
#define G1_B_LD   136
#define G1_A_BYTES (G1_A_ROWS * G1_A_LD * 2)          // 18432 per stage
#define G1_B_BYTES (G1_B_ROWS * G1_B_LD * 2)          // 17408 per stage
#define G1_SMEM (2 * (G1_A_BYTES + G1_B_BYTES))       // 71680

__global__ __launch_bounds__(128, 2)
void k_gemm1(const __half* __restrict__ Gt, const __half* __restrict__ X,
             __half* __restrict__ Y, int col_off, int ldp) {
    extern __shared__ __align__(16) char dsm[];
    __half (*As)[G1_A_ROWS][G1_A_LD] =
        reinterpret_cast<__half(*)[G1_A_ROWS][G1_A_LD]>(dsm);
    __half (*Bs)[G1_B_ROWS][G1_B_LD] =
        reinterpret_cast<__half(*)[G1_B_ROWS][G1_B_LD]>(dsm + 2 * G1_A_BYTES);

    const int s = blockIdx.z;
    const __half* A = Gt + (size_t)s * N_ * N_;
    const int m0 = blockIdx.y * 128;
    const int n0 = col_off + blockIdx.x * 128;
    const int tid = threadIdx.x;
    const int lane = tid & 31;
    const int warp = tid >> 5;
    const int wm = (warp & 1) * 64;
    const int wn = (warp >> 1) * 64;
    const int gq = lane >> 2;
    const int t4 = lane & 3;

    float acc[4][8][4];
#pragma unroll
    for (int i = 0; i < 4; i++)
#pragma unroll
        for (int j = 0; j < 8; j++)
#pragma unroll
            for (int l = 0; l < 4; l++) acc[i][j][l] = 0.f;

    auto load_stage = [&](int buf, int kk0) {
        // A tile 128x64 halves = 1024 cp16 (8/thread)
#pragma unroll
        for (int i = 0; i < 8; i++) {
            int idx = tid + i * 128;
            int row = idx >> 3;
            int seg = (idx & 7) << 3;
            cp16cg(&As[buf][row][seg], A + (size_t)(m0 + row) * N_ + kk0 + seg);
        }
        // B tile 64x128 halves = 1024 cp16 (8/thread)
#pragma unroll
        for (int i = 0; i < 8; i++) {
            int idx = tid + i * 128;
            int r = idx >> 4;
            int seg = (idx & 15) << 3;
            cp16(&Bs[buf][r][seg], X + (size_t)(kk0 + r) * ldp + n0 + seg);
        }
    };

    load_stage(0, 0);
    cp_commit();

    const int KSTEPS = N_ / 64;   // 16
    for (int kt = 0; kt < KSTEPS; kt++) {
        int buf = kt & 1;
        if (kt + 1 < KSTEPS) {
            load_stage(buf ^ 1, (kt + 1) * 64);
            cp_commit();
            cp_wait<1>();
        } else {
            cp_wait<0>();
        }
        __syncthreads();

#pragma unroll
        for (int ks = 0; ks < 4; ks++) {
            const int kb = ks * 16;
            uint32_t a[4][4], b[8][2];
#pragma unroll
            for (int mt = 0; mt < 4; mt++) {
                ldmx4(a[mt], &As[buf][wm + mt * 16 + (lane & 15)]
                                     [kb + (lane >> 4) * 8]);
            }
#pragma unroll
            for (int p = 0; p < 4; p++) {
                uint32_t r[4];
                ldmx4t(r, &Bs[buf][kb + (lane & 7) + ((lane >> 3) & 1) * 8]
                                  [wn + p * 16 + (lane >> 4) * 8]);
                b[2 * p][0] = r[0]; b[2 * p][1] = r[1];
                b[2 * p + 1][0] = r[2]; b[2 * p + 1][1] = r[3];
            }
#pragma unroll
            for (int mt = 0; mt < 4; mt++)
#pragma unroll
                for (int nt = 0; nt < 8; nt++)
                    mma_f16(acc[mt][nt], a[mt], b[nt]);
        }
        __syncthreads();
    }

    // coalesced half2 stores
#pragma unroll
    for (int mt = 0; mt < 4; mt++) {
        int row = m0 + wm + mt * 16 + gq;
#pragma unroll
        for (int nt = 0; nt < 8; nt++) {
            int xcol = n0 + wn + nt * 8 + t4 * 2;
#pragma unroll
            for (int hh = 0; hh < 2; hh++) {
                int rr = row + hh * 8;
                __half2 v = __floats2half2_rn(acc[mt][nt][hh * 2 + 0],
                                              acc[mt][nt][hh * 2 + 1]);
                *(__half2*)&Y[((size_t)s * N_ + rr) * ldp + xcol] = v;
            }
        }
    }
}

// ------------------------- stage-2 gate GEMM (BN=128) ------------------------
// g_zr = sigmoid(A @ Wg + bg). A rows m=(node,b), cols (k,f) padded.
// BM=128, BN=128, BK=32, 4 warps (2x2), warp tile 64x64.
__global__ __launch_bounds__(128, 2)
void k_gemm2g(const __half* __restrict__ Xp, const __half* __restrict__ Yp,
              const __half* __restrict__ W, const float* __restrict__ bias,
              int din_p) {
    __shared__ __align__(16) __half Ask[2][32][136];  // [k][m]
    __shared__ __align__(16) __half Bs[2][32][136];   // [k][n], n=128 + pad

    const int m0 = blockIdx.y * 128;
    const int i0 = m0 >> 6;
    const int tid = threadIdx.x;
    const int lane = tid & 31;
    const int warp = tid >> 5;
    const int wm = (warp & 1) * 64;
    const int wn = (warp >> 1) * 64;
    const int gq = lane >> 2;
    const int t4 = lane & 3;
    const int ldp = din_p * B_;

    float acc[4][8][4];
#pragma unroll
    for (int i = 0; i < 4; i++)
#pragma unroll
        for (int j = 0; j < 8; j++)
#pragma unroll
            for (int l = 0; l < 4; l++) acc[i][j][l] = 0.f;

    auto load_stage = [&](int buf, int kt) {
#pragma unroll
        for (int s16 = 0; s16 < 2; s16++) {
            int kk16 = kt * 32 + s16 * 16;
            int k = kk16 / din_p;
            int f0 = kk16 - k * din_p;
            const __half* basep;
            if (k == 0 || k == 3) basep = Xp;
            else basep = Yp + (size_t)((k < 3) ? k - 1 : k - 2) * N_ * ldp;
            // 16 rows x 128 m halves = 256 cp16 (2/thread)
#pragma unroll
            for (int i = 0; i < 2; i++) {
                int idx = tid + i * 128;
                int j = idx >> 4;
                int q = idx & 15;
                int node = q >> 3;
                int ch = (q & 7) << 3;
                cp16(&Ask[buf][s16 * 16 + j][node * 64 + ch],
                     basep + ((size_t)(i0 + node) * din_p + f0 + j) * B_ + ch);
            }
        }
        // W tile 32x128 halves = 512 cp16 (4/thread)
        {
            int kk0 = kt * 32;
#pragma unroll
            for (int i = 0; i < 4; i++) {
                int idx = tid + i * 128;
                int r = idx >> 4;
                int ch = (idx & 15) << 3;
                cp16(&Bs[buf][r][ch], W + (size_t)(kk0 + r) * 128 + ch);
            }
        }
    };

    load_stage(0, 0);
    cp_commit();

    const int KSTEPS = (K_ * din_p) >> 5;
    for (int kt = 0; kt < KSTEPS; kt++) {
        int buf = kt & 1;
        if (kt + 1 < KSTEPS) {
            load_stage(buf ^ 1, kt + 1);
            cp_commit();
            cp_wait<1>();
        } else {
            cp_wait<0>();
        }
        __syncthreads();

#pragma unroll
        for (int ks = 0; ks < 2; ks++) {
            const int kb = ks * 16;
            uint32_t a[4][4], b[8][2];
#pragma unroll
            for (int mt = 0; mt < 4; mt++) {
                ldmx4t(a[mt], &Ask[buf][kb + (lane & 7) + ((lane >> 4) & 1) * 8]
                                       [wm + mt * 16 + ((lane >> 3) & 1) * 8]);
            }
#pragma unroll
            for (int p = 0; p < 4; p++) {
                uint32_t r[4];
                ldmx4t(r, &Bs[buf][kb + (lane & 7) + ((lane >> 3) & 1) * 8]
                                  [wn + p * 16 + (lane >> 4) * 8]);
                b[2 * p][0] = r[0]; b[2 * p][1] = r[1];
                b[2 * p + 1][0] = r[2]; b[2 * p + 1][1] = r[3];
            }
#pragma unroll
            for (int mt = 0; mt < 4; mt++)
#pragma unroll
                for (int nt = 0; nt < 8; nt++)
                    mma_f16(acc[mt][nt], a[mt], b[nt]);
        }
        __syncthreads();
    }

#pragma unroll
    for (int mt = 0; mt < 4; mt++) {
        int row = m0 + wm + mt * 16 + gq;
#pragma unroll
        for (int nt = 0; nt < 8; nt++) {
            int nb = wn + nt * 8 + t4 * 2;
#pragma unroll
            for (int hh = 0; hh < 2; hh++) {
                size_t m = (size_t)(row + hh * 8);
#pragma unroll
                for (int cc = 0; cc < 2; cc++) {
                    int n = nb + cc;
                    float v = acc[mt][nt][hh * 2 + cc] + bias[n];
                    g_zr[m * (2 * H_) + n] = 1.f / (1.f + expf(-v));
                }
            }
        }
    }
}

// ------------------------- stage-2 update GEMM (BN=64) -----------------------
// hout = z*tanh(A @ Wu + bu) + (1-z)*hprev.
// BM=128, BN=64, BK=32, 4 warps (2x2), warp tile 64x32. 2-stage cp.async.
__global__ __launch_bounds__(128, 2)
void k_gemm2(const __half* __restrict__ Xp, const __half* __restrict__ Yp,
             const __half* __restrict__ W, const float* __restrict__ bias,
             int din_p,
             const float* __restrict__ hprev, float* __restrict__ hout) {
    __shared__ __align__(16) __half Ask[2][32][136];
    __shared__ __align__(16) __half Bs[2][32][72];

    const int m0 = blockIdx.y * 128;
    const int i0 = m0 >> 6;
    const int tid = threadIdx.x;
    const int lane = tid & 31;
    const int warp = tid >> 5;
    const int wm = (warp & 1) * 64;
    const int wn = (warp >> 1) * 32;
    const int gq = lane >> 2;
    const int t4 = lane & 3;
    const int ldp = din_p * B_;

    float acc[4][4][4];
#pragma unroll
    for (int i = 0; i < 4; i++)
#pragma unroll
        for (int j = 0; j < 4; j++)
#pragma unroll
            for (int l = 0; l < 4; l++) acc[i][j][l] = 0.f;

    auto load_stage = [&](int buf, int kt) {
#pragma unroll
        for (int s16 = 0; s16 < 2; s16++) {
            int kk16 = kt * 32 + s16 * 16;
            int k = kk16 / din_p;
            int f0 = kk16 - k * din_p;
            const __half* basep;
            if (k == 0 || k == 3) basep = Xp;
            else basep = Yp + (size_t)((k < 3) ? k - 1 : k - 2) * N_ * ldp;
#pragma unroll
            for (int i = 0; i < 2; i++) {
                int idx = tid + i * 128;
                int j = idx >> 4;
                int q = idx & 15;
                int node = q >> 3;
                int ch = (q & 7) << 3;
                cp16(&Ask[buf][s16 * 16 + j][node * 64 + ch],
                     basep + ((size_t)(i0 + node) * din_p + f0 + j) * B_ + ch);
            }
        }
        // W tile 32x64 halves = 256 cp16 (2/thread)
        {
            int kk0 = kt * 32;
#pragma unroll
            for (int i = 0; i < 2; i++) {
                int idx = tid + i * 128;
                int r = idx >> 3;
                int ch = (idx & 7) << 3;
                cp16(&Bs[buf][r][ch], W + (size_t)(kk0 + r) * 64 + ch);
            }
        }
    };

    load_stage(0, 0);
    cp_commit();

    const int KSTEPS = (K_ * din_p) >> 5;
    for (int kt = 0; kt < KSTEPS; kt++) {
        int buf = kt & 1;
        if (kt + 1 < KSTEPS) {
            load_stage(buf ^ 1, kt + 1);
            cp_commit();
            cp_wait<1>();
        } else {
            cp_wait<0>();
        }
        __syncthreads();

#pragma unroll
        for (int ks = 0; ks < 2; ks++) {
            const int kb = ks * 16;
            uint32_t a[4][4], b[4][2];
#pragma unroll
            for (int mt = 0; mt < 4; mt++) {
                ldmx4t(a[mt], &Ask[buf][kb + (lane & 7) + ((lane >> 4) & 1) * 8]
                                       [wm + mt * 16 + ((lane >> 3) & 1) * 8]);
            }
#pragma unroll
            for (int p = 0; p < 2; p++) {
                uint32_t r[4];
                ldmx4t(r, &Bs[buf][kb + (lane & 7) + ((lane >> 3) & 1) * 8]
                                  [wn + p * 16 + (lane >> 4) * 8]);
                b[2 * p][0] = r[0]; b[2 * p][1] = r[1];
                b[2 * p + 1][0] = r[2]; b[2 * p + 1][1] = r[3];
            }
#pragma unroll
            for (int mt = 0; mt < 4; mt++)
#pragma unroll
                for (int nt = 0; nt < 4; nt++)
                    mma_f16(acc[mt][nt], a[mt], b[nt]);
        }
        __syncthreads();
    }

#pragma unroll
    for (int mt = 0; mt < 4; mt++) {
        int row = m0 + wm + mt * 16 + gq;
#pragma unroll
        for (int nt = 0; nt < 4; nt++) {
            int nb = wn + nt * 8 + t4 * 2;
#pragma unroll
            for (int hh = 0; hh < 2; hh++) {
                size_t m = (size_t)(row + hh * 8);
#pragma unroll
                for (int cc = 0; cc < 2; cc++) {
                    int n = nb + cc;
                    float v = acc[mt][nt][hh * 2 + cc] + bias[n];
                    float z = g_zr[m * (2 * H_) + n];
                    float hold = hprev ? hprev[m * H_ + n] : 0.f;
                    hout[m * H_ + n] = z * tanhf(v) + (1.f - z) * hold;
                }
            }
        }
    }
}

// Projection + output scatter + decoder feedback.
__global__ void k_proj(const float* __restrict__ projW,
                       const float* __restrict__ projb,
                       int t, float* __restrict__ out) {
    int m = blockIdx.x * blockDim.x + threadIdx.x;
    if (m >= M_) return;
    int i = m / B_;
    int b = m - i * B_;
    float a0 = projb[0], a1 = projb[1];
    const float* hv = &g_hB[(size_t)m * H_];
#pragma unroll
    for (int j = 0; j < H_; j++) {
        float h = hv[j];
        a0 += h * projW[j * 2 + 0];
        a1 += h * projW[j * 2 + 1];
    }
    g_y[(size_t)m * C_ + 0] = a0;
    g_y[(size_t)m * C_ + 1] = a1;
    size_t o = ((((size_t)b * HOR_ + t) * N_) + i) * C_;
    out[o + 0] = a0;
    out[o + 1] = a1;
}

// ------------------------------ host side -----------------------------------

static inline int cdiv(int a, int b) { return (a + b - 1) / b; }

// padded weight offsets inside g_Wp (element counts)
#define OFF_E0G 0
#define OFF_E0U 61440
#define OFF_D0G 92160
#define OFF_D0U 153600
#define OFF_E1G 184320
#define OFF_E1U 282624
#define OFF_D1G 331776
#define OFF_D1U 430080

static void cell_gate_start(const __half* Gt, const float* xin, int dinx,
                            const float* hprev, __half* Xp, __half* Yp,
                            int din_r, int din_p) {
    const int ldp = din_p * B_;
    k_concat_full<<<cdiv(N_ * din_r * B_, 256), 256>>>(xin, dinx, hprev,
                                                       Xp, din_r, din_p);
    dim3 g1((din_r * B_) / 128, N_ / 128, 4);
    k_gemm1<<<g1, 128, G1_SMEM>>>(Gt, Xp, Yp, 0, ldp);
}

static void cell_rest(const __half* Gt, int dinx,
                      const float* hprev, float* hout,
                      const __half* Wg, const float* bg,
                      const __half* Wu, const float* bu,
                      __half* Xp, __half* Yp, int din_p) {
    const int ldp = din_p * B_;
    k_gemm2g<<<dim3(1, M_ / 128), 128>>>(Xp, Yp, Wg, bg, din_p);
    k_concat_h<<<cdiv(N_ * H_ * B_, 256), 256>>>(hprev, dinx, Xp, din_p);
    dim3 g1h((H_ * B_) / 128, N_ / 128, 4);
    k_gemm1<<<g1h, 128, G1_SMEM>>>(Gt, Xp, Yp, dinx * B_, ldp);
    k_gemm2<<<dim3(1, M_ / 128), 128>>>(Xp, Yp, Wu, bu, din_p, hprev, hout);
}

static void run_cell(const __half* Gt, const float* xin, int dinx,
                     const float* hprev, float* hout,
                     const __half* Wg, const float* bg,
                     const __half* Wu, const float* bu,
                     __half* Xp, __half* Yp, int din_r, int din_p) {
    cell_gate_start(Gt, xin, dinx, hprev, Xp, Yp, din_r, din_p);
    cell_rest(Gt, dinx, hprev, hout, Wg, bg, Wu, bu, Xp, Yp, din_p);
}

extern "C" void kernel_launch(void* const* d_in, const int* in_sizes, int n_in,
                              void* d_out, int out_size) {
    (void)in_sizes; (void)n_in; (void)out_size;

    const float* x = (const float*)d_in[0];
    const float* G = (const float*)d_in[1];
    const float* w[16];
    for (int i = 0; i < 16; i++) w[i] = (const float*)d_in[2 + i];
    const float* projW = (const float*)d_in[18];
    const float* projb = (const float*)d_in[19];
    float* out = (float*)d_out;

    cudaFuncSetAttribute(k_gemm1, cudaFuncAttributeMaxDynamicSharedMemorySize,
                         G1_SMEM);

    float *p_xT, *p_seq, *p_hA, *p_hB, *p_y;
    __half *p_X0, *p_X1, *p_Y0, *p_Y1, *p_Gt, *p_Wp;
    cudaGetSymbolAddress((void**)&p_xT,  g_xT);
    cudaGetSymbolAddress((void**)&p_seq, g_seq);
    cudaGetSymbolAddress((void**)&p_hA,  g_hA);
    cudaGetSymbolAddress((void**)&p_hB,  g_hB);
    cudaGetSymbolAddress((void**)&p_y,   g_y);
    cudaGetSymbolAddress((void**)&p_X0,  g_X0);
    cudaGetSymbolAddress((void**)&p_X1,  g_X1);
    cudaGetSymbolAddress((void**)&p_Y0,  g_Y0);
    cudaGetSymbolAddress((void**)&p_Y1,  g_Y1);
    cudaGetSymbolAddress((void**)&p_Gt,  g_Gt);
    cudaGetSymbolAddress((void**)&p_Wp,  g_Wp);

    // prep
    k_prep_G<<<cdiv(4 * N_ * N_, 256), 256>>>(G);
    {
        int total = B_ * T_ * N_ * C_;
        k_transpose_x<<<cdiv(total, 256), 256>>>(x);
    }
    k_prep_W<<<cdiv(K_ * DINP0 * 128, 256), 256>>>(w[0], p_Wp + OFF_E0G,
                                                   DINR0, DINP0, 128);
    k_prep_W<<<cdiv(K_ * DINP0 *  64, 256), 256>>>(w[2], p_Wp + OFF_E0U,
                                                   DINR0, DINP0,  64);
    // enc0 t=0 gate pass start
    cell_gate_start(p_Gt, p_xT, C_, nullptr, p_X0, p_Y0, DINR0, DINP0);

    // remaining weight prep (stream-ordered before first use)
    k_prep_W<<<cdiv(K_ * DINP1 * 128, 256), 256>>>(w[4],  p_Wp + OFF_E1G, DINR1, DINP1, 128);
    k_prep_W<<<cdiv(K_ * DINP1 *  64, 256), 256>>>(w[6],  p_Wp + OFF_E1U, DINR1, DINP1,  64);
    k_prep_W<<<cdiv(K_ * DINP0 * 128, 256), 256>>>(w[8],  p_Wp + OFF_D0G, DINR0, DINP0, 128);
    k_prep_W<<<cdiv(K_ * DINP0 *  64, 256), 256>>>(w[10], p_Wp + OFF_D0U, DINR0, DINP0,  64);
    k_prep_W<<<cdiv(K_ * DINP1 * 128, 256), 256>>>(w[12], p_Wp + OFF_D1G, DINR1, DINP1, 128);
    k_prep_W<<<cdiv(K_ * DINP1 *  64, 256), 256>>>(w[14], p_Wp + OFF_D1U, DINR1, DINP1,  64);

    // finish enc0 t=0
    cell_rest(p_Gt, C_, nullptr, p_seq,
              p_Wp + OFF_E0G, w[1], p_Wp + OFF_E0U, w[3],
              p_X0, p_Y0, DINP0);

    // encoder layer 0, t=1..11
    for (int t = 1; t < T_; t++) {
        const float* xin   = p_xT + (size_t)t * N_ * B_ * C_;
        const float* hprev = p_seq + (size_t)(t - 1) * NBH_;
        float* hout        = p_seq + (size_t)t * NBH_;
        run_cell(p_Gt, xin, C_, hprev, hout,
                 p_Wp + OFF_E0G, w[1], p_Wp + OFF_E0U, w[3],
                 p_X0, p_Y0, DINR0, DINP0);
    }

    // encoder layer 1 (din 128)
    for (int t = 0; t < T_; t++) {
        const float* xin   = p_seq + (size_t)t * NBH_;
        const float* hprev = (t == 0) ? nullptr : p_hB;
        run_cell(p_Gt, xin, H_, hprev, p_hB,
                 p_Wp + OFF_E1G, w[5], p_Wp + OFF_E1U, w[7],
                 p_X1, p_Y1, DINR1, DINP1);
    }

    // decoder feedback init
    cudaMemsetAsync(p_y, 0, (size_t)M_ * C_ * sizeof(float));

    // decoder loop
    for (int t = 0; t < HOR_; t++) {
        const float* h0prev = (t == 0) ? (p_seq + (size_t)(T_ - 1) * NBH_)
                                       : p_hA;
        run_cell(p_Gt, p_y, C_, h0prev, p_hA,
                 p_Wp + OFF_D0G, w[9], p_Wp + OFF_D0U, w[11],
                 p_X0, p_Y0, DINR0, DINP0);
        run_cell(p_Gt, p_hA, H_, p_hB, p_hB,
                 p_Wp + OFF_D1G, w[13], p_Wp + OFF_D1U, w[15],
                 p_X1, p_Y1, DINR1, DINP1);
        k_proj<<<cdiv(M_, 256), 256>>>(projW, projb, t, out);
    }
}

// round 12
// speedup vs baseline: 1.0818x; 1.0818x over previous
#include <cuda_runtime.h>
#include <cuda_fp16.h>
#include <math.h>
#include <stdint.h>

// ---------------------------------------------------------------------------
// GCGRU encoder-decoder. FP16 legacy tensor cores (mma.m16n8k16, fp32 accum),
// ldmatrix fragment loads, 2-stage cp.async double buffering (R10 config).
// R12: concat fused into GEMM epilogues:
//   - k_gemm2g writes zr AND Xp h-cols = r*h   (kills k_concat_h)
//   - k_gemm2  writes hout AND Xp h-cols = h'  (next cell needs x-cols only)
//
// Layouts (all half):
//   g_X*  : (N, din_p, B)        stage-1 input, pad cols zero
//   g_Y*  : (slot, N, din_p, B)  stage-1 output for supports {1,2,4,5};
//                                identity supports (0,3) read from g_X.
//   g_Gt  : (slot, N, N)         4 non-identity supports
//   g_Wp  : padded (K*din_p, outd) weights
// ---------------------------------------------------------------------------

#define N_    1024
#define B_    64
#define T_    12
#define HOR_  12
#define C_    2
#define H_    64
#define K_    6

#define NBH_  (N_ * B_ * H_)
#define M_    (N_ * B_)

#define DINR0 66
#define DINP0 80
#define DINR1 128
#define DINP1 128

// ------------------------- scratch (device globals) -------------------------
__device__ float  g_xT[T_ * N_ * B_ * C_];
__device__ float  g_seq[T_ * N_ * B_ * H_];
__device__ float  g_hA[NBH_];
__device__ float  g_hB[NBH_];
__device__ __half g_X0[N_ * DINP0 * B_];
__device__ __half g_X1[N_ * DINP1 * B_];
__device__ __half g_Y0[4ll * N_ * DINP0 * B_];
__device__ __half g_Y1[4ll * N_ * DINP1 * B_];
__device__ float  g_zr[(size_t)M_ * 2 * H_];
__device__ float  g_y[M_ * C_];
__device__ __half g_Gt[4 * N_ * N_];
__device__ __half g_Wp[479232];

// ------------------------------ helpers -------------------------------------
__device__ __forceinline__ void mma_f16(float* c, const uint32_t* a,
                                        const uint32_t* b) {
    asm volatile(
        "mma.sync.aligned.m16n8k16.row.col.f32.f16.f16.f32 "
        "{%0,%1,%2,%3}, {%4,%5,%6,%7}, {%8,%9}, {%0,%1,%2,%3};\n"
        : "+f"(c[0]), "+f"(c[1]), "+f"(c[2]), "+f"(c[3])
        : "r"(a[0]), "r"(a[1]), "r"(a[2]), "r"(a[3]), "r"(b[0]), "r"(b[1]));
}

__device__ __forceinline__ void ldmx4(uint32_t* r, const void* p) {
    uint32_t a = (uint32_t)__cvta_generic_to_shared(p);
    asm volatile("ldmatrix.sync.aligned.m8n8.x4.shared.b16 {%0,%1,%2,%3}, [%4];"
                 : "=r"(r[0]), "=r"(r[1]), "=r"(r[2]), "=r"(r[3]) : "r"(a));
}
__device__ __forceinline__ void ldmx4t(uint32_t* r, const void* p) {
    uint32_t a = (uint32_t)__cvta_generic_to_shared(p);
    asm volatile("ldmatrix.sync.aligned.m8n8.x4.trans.shared.b16 {%0,%1,%2,%3}, [%4];"
                 : "=r"(r[0]), "=r"(r[1]), "=r"(r[2]), "=r"(r[3]) : "r"(a));
}

__device__ __forceinline__ void cp16(void* dst, const void* src) {
    uint32_t d = (uint32_t)__cvta_generic_to_shared(dst);
    asm volatile("cp.async.ca.shared.global [%0], [%1], 16;\n"
                 :: "r"(d), "l"(src));
}
__device__ __forceinline__ void cp16cg(void* dst, const void* src) {
    uint32_t d = (uint32_t)__cvta_generic_to_shared(dst);
    asm volatile("cp.async.cg.shared.global [%0], [%1], 16;\n"
                 :: "r"(d), "l"(src));
}
__device__ __forceinline__ void cp_commit() {
    asm volatile("cp.async.commit_group;\n");
}
template <int n>
__device__ __forceinline__ void cp_wait() {
    asm volatile("cp.async.wait_group %0;\n" :: "n"(n));
}

// ------------------------------ prep kernels --------------------------------

__global__ void k_prep_G(const float* __restrict__ G) {
    int idx = blockIdx.x * blockDim.x + threadIdx.x;
    if (idx >= 4 * N_ * N_) return;
    int s = idx / (N_ * N_);
    int r = idx - s * (N_ * N_);
    int kidx = s + 1 + (s >> 1);   // {1,2,4,5}
    g_Gt[idx] = __float2half_rn(G[(size_t)kidx * N_ * N_ + r]);
}

__global__ void k_prep_W(const float* __restrict__ src, __half* __restrict__ dst,
                         int din_r, int din_p, int outd) {
    int idx = blockIdx.x * blockDim.x + threadIdx.x;
    int total = K_ * din_p * outd;
    if (idx >= total) return;
    int o = idx % outd;
    int row = idx / outd;
    int k = row / din_p;
    int f = row - k * din_p;
    dst[idx] = (f < din_r) ? __float2half_rn(src[(size_t)(k * din_r + f) * outd + o])
                           : __float2half_rn(0.f);
}

// ------------------------------ data movement -------------------------------

// x (B,T,N,C) -> g_xT (T,N,B,C)
__global__ void k_transpose_x(const float* __restrict__ x) {
    int idx = blockIdx.x * blockDim.x + threadIdx.x;
    const int total = B_ * T_ * N_ * C_;
    if (idx >= total) return;
    int c = idx % C_;
    int i = (idx / C_) % N_;
    int t = (idx / (C_ * N_)) % T_;
    int b = idx / (C_ * N_ * T_);
    g_xT[(((size_t)t * N_ + i) * B_ + b) * C_ + c] = x[idx];
}

// Full concat (t=0 cells only): X[i][f][b] = concat(x, h) with h possibly null.
__global__ void k_concat_full(const float* __restrict__ xin, int dinx,
                              const float* __restrict__ h,
                              __half* __restrict__ X, int din_r, int din_p) {
    int idx = blockIdx.x * blockDim.x + threadIdx.x;
    int total = N_ * din_r * B_;
    if (idx >= total) return;
    int b = idx & 63;
    int f = (idx >> 6) % din_r;
    int i = idx / (64 * din_r);
    int m = i * B_ + b;
    float v;
    if (f < dinx) v = xin[(size_t)m * dinx + f];
    else          v = h ? h[(size_t)m * H_ + (f - dinx)] : 0.f;
    X[((size_t)i * din_p + f) * B_ + b] = __float2half_rn(v);
}

// X-columns-only concat (steady state): X[i][f][b] = xin[m][f], f < dinx.
__global__ void k_concat_x(const float* __restrict__ xin, int dinx,
                           __half* __restrict__ X, int din_p) {
    int idx = blockIdx.x * blockDim.x + threadIdx.x;
    int total = N_ * dinx * B_;
    if (idx >= total) return;
    int b = idx & 63;
    int f = (idx >> 6) % dinx;
    int i = idx / (64 * dinx);
    int m = i * B_ + b;
    X[((size_t)i * din_p + f) * B_ + b] =
        __float2half_rn(xin[(size_t)m * dinx + f]);
}

// ------------------------------ stage-1 GEMM --------------------------------
// Y[s] = G[s] @ X over columns [col_off, col_off + gridX*128).
// BM=128, BN=128, BK=64, 8 warps (4x2), warp tile 32x64, fp16 mma m16n8k16.
// 2-stage cp.async double buffering in dynamic smem; 16 K-iterations.
#define G1_A_ROWS 128
#define G1_A_LD   72
#define G1_B_ROWS 64
#define G1_B_LD   136
#define G1_A_BYTES (G1_A_ROWS * G1_A_LD * 2)
#define G1_B_BYTES (G1_B_ROWS * G1_B_LD * 2)
#define G1_SMEM (2 * (G1_A_BYTES + G1_B_BYTES))   // 71680

__global__ __launch_bounds__(256)
void k_gemm1(const __half* __restrict__ Gt, const __half* __restrict__ X,
             __half* __restrict__ Y, int col_off, int ldp) {
    extern __shared__ __align__(16) char dsm[];
    __half (*As)[G1_A_ROWS][G1_A_LD] =
        reinterpret_cast<__half(*)[G1_A_ROWS][G1_A_LD]>(dsm);
    __half (*Bs)[G1_B_ROWS][G1_B_LD] =
        reinterpret_cast<__half(*)[G1_B_ROWS][G1_B_LD]>(dsm + 2 * G1_A_BYTES);

    const int s = blockIdx.z;
    const __half* A = Gt + (size_t)s * N_ * N_;
    const int m0 = blockIdx.y * 128;
    const int n0 = col_off + blockIdx.x * 128;
    const int tid = threadIdx.x;
    const int lane = tid & 31;
    const int warp = tid >> 5;
    const int wm = (warp & 3) * 32;
    const int wn = (warp >> 2) * 64;
    const int gq = lane >> 2;
    const int t4 = lane & 3;

    float acc[2][8][4];
#pragma unroll
    for (int i = 0; i < 2; i++)
#pragma unroll
        for (int j = 0; j < 8; j++)
#pragma unroll
            for (int l = 0; l < 4; l++) acc[i][j][l] = 0.f;

    auto load_stage = [&](int buf, int kk0) {
#pragma unroll
        for (int i = 0; i < 4; i++) {
            int idx = tid + i * 256;
            int row = idx >> 3;
            int seg = (idx & 7) << 3;
            cp16cg(&As[buf][row][seg], A + (size_t)(m0 + row) * N_ + kk0 + seg);
        }
#pragma unroll
        for (int i = 0; i < 4; i++) {
            int idx = tid + i * 256;
            int r = idx >> 4;
            int seg = (idx & 15) << 3;
            cp16(&Bs[buf][r][seg], X + (size_t)(kk0 + r) * ldp + n0 + seg);
        }
    };

    load_stage(0, 0);
    cp_commit();

    const int KSTEPS = N_ / 64;   // 16
    for (int kt = 0; kt < KSTEPS; kt++) {
        int buf = kt & 1;
        if (kt + 1 < KSTEPS) {
            load_stage(buf ^ 1, (kt + 1) * 64);
            cp_commit();
            cp_wait<1>();
        } else {
            cp_wait<0>();
        }
        __syncthreads();

#pragma unroll
        for (int ks = 0; ks < 4; ks++) {
            const int kb = ks * 16;
            uint32_t a[2][4], b[8][2];
#pragma unroll
            for (int mt = 0; mt < 2; mt++) {
                ldmx4(a[mt], &As[buf][wm + mt * 16 + (lane & 15)]
                                     [kb + (lane >> 4) * 8]);
            }
#pragma unroll
            for (int p = 0; p < 4; p++) {
                uint32_t r[4];
                ldmx4t(r, &Bs[buf][kb + (lane & 7) + ((lane >> 3) & 1) * 8]
                                  [wn + p * 16 + (lane >> 4) * 8]);
                b[2 * p][0] = r[0]; b[2 * p][1] = r[1];
                b[2 * p + 1][0] = r[2]; b[2 * p + 1][1] = r[3];
            }
#pragma unroll
            for (int mt = 0; mt < 2; mt++)
#pragma unroll
                for (int nt = 0; nt < 8; nt++)
                    mma_f16(acc[mt][nt], a[mt], b[nt]);
        }
        __syncthreads();
    }

#pragma unroll
    for (int mt = 0; mt < 2; mt++) {
        int row = m0 + wm + mt * 16 + gq;
#pragma unroll
        for (int nt = 0; nt < 8; nt++) {
            int xcol = n0 + wn + nt * 8 + t4 * 2;
#pragma unroll
            for (int hh = 0; hh < 2; hh++) {
                int rr = row + hh * 8;
                __half2 v = __floats2half2_rn(acc[mt][nt][hh * 2 + 0],
                                              acc[mt][nt][hh * 2 + 1]);
                *(__half2*)&Y[((size_t)s * N_ + rr) * ldp + xcol] = v;
            }
        }
    }
}

// ------------------------- stage-2 gate GEMM (BN=128) ------------------------
// zr = sigmoid(A @ Wg + bg); FUSED: Xh h-cols <- r * hprev (candidate input).
// BM=128, BN=128, BK=32, 8 warps (4x2), warp tile 32x64.
__global__ __launch_bounds__(256)
void k_gemm2g(const __half* __restrict__ Xp, const __half* __restrict__ Yp,
              const __half* __restrict__ W, const float* __restrict__ bias,
              int din_p, const float* __restrict__ hprev,
              __half* __restrict__ Xh, int dinx) {
    __shared__ __align__(16) __half Ask[2][32][136];
    __shared__ __align__(16) __half Bs[2][32][136];

    const int m0 = blockIdx.y * 128;
    const int i0 = m0 >> 6;
    const int tid = threadIdx.x;
    const int lane = tid & 31;
    const int warp = tid >> 5;
    const int wm = (warp & 3) * 32;
    const int wn = (warp >> 2) * 64;
    const int gq = lane >> 2;
    const int t4 = lane & 3;
    const int ldp = din_p * B_;

    float acc[2][8][4];
#pragma unroll
    for (int i = 0; i < 2; i++)
#pragma unroll
        for (int j = 0; j < 8; j++)
#pragma unroll
            for (int l = 0; l < 4; l++) acc[i][j][l] = 0.f;

    auto load_stage = [&](int buf, int kt) {
#pragma unroll
        for (int s16 = 0; s16 < 2; s16++) {
            int kk16 = kt * 32 + s16 * 16;
            int k = kk16 / din_p;
            int f0 = kk16 - k * din_p;
            const __half* basep;
            if (k == 0 || k == 3) basep = Xp;
            else basep = Yp + (size_t)((k < 3) ? k - 1 : k - 2) * N_ * ldp;
            int j = tid >> 4;
            int q = tid & 15;
            int node = q >> 3;
            int ch = (q & 7) << 3;
            cp16(&Ask[buf][s16 * 16 + j][node * 64 + ch],
                 basep + ((size_t)(i0 + node) * din_p + f0 + j) * B_ + ch);
        }
        {
            int kk0 = kt * 32;
#pragma unroll
            for (int i = 0; i < 2; i++) {
                int idx = tid + i * 256;
                int r = idx >> 4;
                int ch = (idx & 15) << 3;
                cp16(&Bs[buf][r][ch], W + (size_t)(kk0 + r) * 128 + ch);
            }
        }
    };

    load_stage(0, 0);
    cp_commit();

    const int KSTEPS = (K_ * din_p) >> 5;
    for (int kt = 0; kt < KSTEPS; kt++) {
        int buf = kt & 1;
        if (kt + 1 < KSTEPS) {
            load_stage(buf ^ 1, kt + 1);
            cp_commit();
            cp_wait<1>();
        } else {
            cp_wait<0>();
        }
        __syncthreads();

#pragma unroll
        for (int ks = 0; ks < 2; ks++) {
            const int kb = ks * 16;
            uint32_t a[2][4], b[8][2];
#pragma unroll
            for (int mt = 0; mt < 2; mt++) {
                ldmx4t(a[mt], &Ask[buf][kb + (lane & 7) + ((lane >> 4) & 1) * 8]
                                       [wm + mt * 16 + ((lane >> 3) & 1) * 8]);
            }
#pragma unroll
            for (int p = 0; p < 4; p++) {
                uint32_t r[4];
                ldmx4t(r, &Bs[buf][kb + (lane & 7) + ((lane >> 3) & 1) * 8]
                                  [wn + p * 16 + (lane >> 4) * 8]);
                b[2 * p][0] = r[0]; b[2 * p][1] = r[1];
                b[2 * p + 1][0] = r[2]; b[2 * p + 1][1] = r[3];
            }
#pragma unroll
            for (int mt = 0; mt < 2; mt++)
#pragma unroll
                for (int nt = 0; nt < 8; nt++)
                    mma_f16(acc[mt][nt], a[mt], b[nt]);
        }
        __syncthreads();
    }

#pragma unroll
    for (int mt = 0; mt < 2; mt++) {
        int row = m0 + wm + mt * 16 + gq;
#pragma unroll
        for (int nt = 0; nt < 8; nt++) {
            int nb = wn + nt * 8 + t4 * 2;
#pragma unroll
            for (int hh = 0; hh < 2; hh++) {
                size_t m = (size_t)(row + hh * 8);
#pragma unroll
                for (int cc = 0; cc < 2; cc++) {
                    int n = nb + cc;
                    float v = acc[mt][nt][hh * 2 + cc] + bias[n];
                    float sig = 1.f / (1.f + expf(-v));
                    g_zr[m * (2 * H_) + n] = sig;
                    if (n >= H_) {
                        int j = n - H_;
                        float hv = hprev ? hprev[m * H_ + j] : 0.f;
                        Xh[((size_t)(m >> 6) * din_p + dinx + j) * B_ +
                           (m & 63)] = __float2half_rn(sig * hv);
                    }
                }
            }
        }
    }
}

// ------------------------- stage-2 update GEMM (BN=64) -----------------------
// h' = z*tanh(A @ Wu + bu) + (1-z)*hprev; FUSED: Xh h-cols <- h' (next cell).
// BM=128, BN=64, BK=32, 8 warps (4x2), warp tile 32x32. 2-stage cp.async.
__global__ __launch_bounds__(256)
void k_gemm2(const __half* __restrict__ Xp, const __half* __restrict__ Yp,
             const __half* __restrict__ W, const float* __restrict__ bias,
             int din_p,
             const float* __restrict__ hprev, float* __restrict__ hout,
             __half* __restrict__ Xh, int dinx) {
    __shared__ __align__(16) __half Ask[2][32][136];
    __shared__ __align__(16) __half Bs[2][32][72];

    const int m0 = blockIdx.y * 128;
    const int i0 = m0 >> 6;
    const int tid = threadIdx.x;
    const int lane = tid & 31;
    const int warp = tid >> 5;
    const int wm = (warp & 3) * 32;
    const int wn = (warp >> 2) * 32;
    const int gq = lane >> 2;
    const int t4 = lane & 3;
    const int ldp = din_p * B_;

    float acc[2][4][4];
#pragma unroll
    for (int i = 0; i < 2; i++)
#pragma unroll
        for (int j = 0; j < 4; j++)
#pragma unroll
            for (int l = 0; l < 4; l++) acc[i][j][l] = 0.f;

    auto load_stage = [&](int buf, int kt) {
#pragma unroll
        for (int s16 = 0; s16 < 2; s16++) {
            int kk16 = kt * 32 + s16 * 16;
            int k = kk16 / din_p;
            int f0 = kk16 - k * din_p;
            const __half* basep;
            if (k == 0 || k == 3) basep = Xp;
            else basep = Yp + (size_t)((k < 3) ? k - 1 : k - 2) * N_ * ldp;
            int j = tid >> 4;
            int q = tid & 15;
            int node = q >> 3;
            int ch = (q & 7) << 3;
            cp16(&Ask[buf][s16 * 16 + j][node * 64 + ch],
                 basep + ((size_t)(i0 + node) * din_p + f0 + j) * B_ + ch);
        }
        {
            int kk0 = kt * 32;
            int r = tid >> 3;
            int ch = (tid & 7) << 3;
            cp16(&Bs[buf][r][ch], W + (size_t)(kk0 + r) * 64 + ch);
        }
    };

    load_stage(0, 0);
    cp_commit();

    const int KSTEPS = (K_ * din_p) >> 5;
    for (int kt = 0; kt < KSTEPS; kt++) {
        int buf = kt & 1;
        if (kt + 1 < KSTEPS) {
            load_stage(buf ^ 1, kt + 1);
            cp_commit();
            cp_wait<1>();
        } else {
            cp_wait<0>();
        }
        __syncthreads();

#pragma unroll
        for (int ks = 0; ks < 2; ks++) {
            const int kb = ks * 16;
            uint32_t a[2][4], b[4][2];
#pragma unroll
            for (int mt = 0; mt < 2; mt++) {
                ldmx4t(a[mt], &Ask[buf][kb + (lane & 7) + ((lane >> 4) & 1) * 8]
                                       [wm + mt * 16 + ((lane >> 3) & 1) * 8]);
            }
#pragma unroll
            for (int p = 0; p < 2; p++) {
                uint32_t r[4];
                ldmx4t(r, &Bs[buf][kb + (lane & 7) + ((lane >> 3) & 1) * 8]
                                  [wn + p * 16 + (lane >> 4) * 8]);
                b[2 * p][0] = r[0]; b[2 * p][1] = r[1];
                b[2 * p + 1][0] = r[2]; b[2 * p + 1][1] = r[3];
            }
#pragma unroll
            for (int mt = 0; mt < 2; mt++)
#pragma unroll
                for (int nt = 0; nt < 4; nt++)
                    mma_f16(acc[mt][nt], a[mt], b[nt]);
        }
        __syncthreads();
    }

#pragma unroll
    for (int mt = 0; mt < 2; mt++) {
        int row = m0 + wm + mt * 16 + gq;
#pragma unroll
        for (int nt = 0; nt < 4; nt++) {
            int nb = wn + nt * 8 + t4 * 2;
#pragma unroll
            for (int hh = 0; hh < 2; hh++) {
                size_t m = (size_t)(row + hh * 8);
#pragma unroll
                for (int cc = 0; cc < 2; cc++) {
                    int n = nb + cc;
                    float v = acc[mt][nt][hh * 2 + cc] + bias[n];
                    float z = g_zr[m * (2 * H_) + n];
                    float hold = hprev ? hprev[m * H_ + n] : 0.f;
                    float hnew = z * tanhf(v) + (1.f - z) * hold;
                    hout[m * H_ + n] = hnew;
                    Xh[((size_t)(m >> 6) * din_p + dinx + n) * B_ + (m & 63)] =
                        __float2half_rn(hnew);
                }
            }
        }
    }
}

// Projection + output scatter + decoder feedback.
__global__ void k_proj(const float* __restrict__ projW,
                       const float* __restrict__ projb,
                       int t, float* __restrict__ out) {
    int m = blockIdx.x * blockDim.x + threadIdx.x;
    if (m >= M_) return;
    int i = m / B_;
    int b = m - i * B_;
    float a0 = projb[0], a1 = projb[1];
    const float* hv = &g_hB[(size_t)m * H_];
#pragma unroll
    for (int j = 0; j < H_; j++) {
        float h = hv[j];
        a0 += h * projW[j * 2 + 0];
        a1 += h * projW[j * 2 + 1];
    }
    g_y[(size_t)m * C_ + 0] = a0;
    g_y[(size_t)m * C_ + 1] = a1;
    size_t o = ((((size_t)b * HOR_ + t) * N_) + i) * C_;
    out[o + 0] = a0;
    out[o + 1] = a1;
}

// ------------------------------ host side -----------------------------------

static inline int cdiv(int a, int b) { return (a + b - 1) / b; }

// padded weight offsets inside g_Wp (element counts)
#define OFF_E0G 0
#define OFF_E0U 61440
#define OFF_D0G 92160
#define OFF_D0U 153600
#define OFF_E1G 184320
#define OFF_E1U 282624
#define OFF_D1G 331776
#define OFF_D1U 430080

// One GRU cell. concat_mode: 0 = full concat (t=0), 1 = x-cols only,
// 2 = none needed besides x-cols (same as 1). hprev may be null (t=0).
static void run_cell(const __half* Gt, const float* xin, int dinx,
                     const float* hprev, float* hout,
                     const __half* Wg, const float* bg,
                     const __half* Wu, const float* bu,
                     __half* Xp, __half* Yp, int din_r, int din_p,
                     bool full_concat) {
    const int ldp = din_p * B_;

    // input build: x-cols always; h-cols only at t=0 (zeros/h from scratch)
    if (full_concat) {
        k_concat_full<<<cdiv(N_ * din_r * B_, 256), 256>>>(xin, dinx, hprev,
                                                           Xp, din_r, din_p);
    } else {
        k_concat_x<<<cdiv(N_ * dinx * B_, 256), 256>>>(xin, dinx, Xp, din_p);
    }

    // gate pass
    dim3 g1((din_r * B_) / 128, N_ / 128, 4);
    k_gemm1<<<g1, 256, G1_SMEM>>>(Gt, Xp, Yp, 0, ldp);
    k_gemm2g<<<dim3(1, M_ / 128), 256>>>(Xp, Yp, Wg, bg, din_p,
                                         hprev, Xp, dinx);   // fused r*h -> Xp

    // candidate pass (h columns recomputed from fused r*h)
    dim3 g1h((H_ * B_) / 128, N_ / 128, 4);
    k_gemm1<<<g1h, 256, G1_SMEM>>>(Gt, Xp, Yp, dinx * B_, ldp);
    k_gemm2<<<dim3(1, M_ / 128), 256>>>(Xp, Yp, Wu, bu, din_p,
                                        hprev, hout, Xp, dinx); // fused h'->Xp
}

extern "C" void kernel_launch(void* const* d_in, const int* in_sizes, int n_in,
                              void* d_out, int out_size) {
    (void)in_sizes; (void)n_in; (void)out_size;

    const float* x = (const float*)d_in[0];
    const float* G = (const float*)d_in[1];
    const float* w[16];
    for (int i = 0; i < 16; i++) w[i] = (const float*)d_in[2 + i];
    const float* projW = (const float*)d_in[18];
    const float* projb = (const float*)d_in[19];
    float* out = (float*)d_out;

    cudaFuncSetAttribute(k_gemm1, cudaFuncAttributeMaxDynamicSharedMemorySize,
                         G1_SMEM);

    float *p_xT, *p_seq, *p_hA, *p_hB, *p_y;
    __half *p_X0, *p_X1, *p_Y0, *p_Y1, *p_Gt, *p_Wp;
    cudaGetSymbolAddress((void**)&p_xT,  g_xT);
    cudaGetSymbolAddress((void**)&p_seq, g_seq);
    cudaGetSymbolAddress((void**)&p_hA,  g_hA);
    cudaGetSymbolAddress((void**)&p_hB,  g_hB);
    cudaGetSymbolAddress((void**)&p_y,   g_y);
    cudaGetSymbolAddress((void**)&p_X0,  g_X0);
    cudaGetSymbolAddress((void**)&p_X1,  g_X1);
    cudaGetSymbolAddress((void**)&p_Y0,  g_Y0);
    cudaGetSymbolAddress((void**)&p_Y1,  g_Y1);
    cudaGetSymbolAddress((void**)&p_Gt,  g_Gt);
    cudaGetSymbolAddress((void**)&p_Wp,  g_Wp);

    // prep
    k_prep_G<<<cdiv(4 * N_ * N_, 256), 256>>>(G);
    {
        int total = B_ * T_ * N_ * C_;
        k_transpose_x<<<cdiv(total, 256), 256>>>(x);
    }
    k_prep_W<<<cdiv(K_ * DINP0 * 128, 256), 256>>>(w[0],  p_Wp + OFF_E0G, DINR0, DINP0, 128);
    k_prep_W<<<cdiv(K_ * DINP0 *  64, 256), 256>>>(w[2],  p_Wp + OFF_E0U, DINR0, DINP0,  64);
    k_prep_W<<<cdiv(K_ * DINP1 * 128, 256), 256>>>(w[4],  p_Wp + OFF_E1G, DINR1, DINP1, 128);
    k_prep_W<<<cdiv(K_ * DINP1 *  64, 256), 256>>>(w[6],  p_Wp + OFF_E1U, DINR1, DINP1,  64);
    k_prep_W<<<cdiv(K_ * DINP0 * 128, 256), 256>>>(w[8],  p_Wp + OFF_D0G, DINR0, DINP0, 128);
    k_prep_W<<<cdiv(K_ * DINP0 *  64, 256), 256>>>(w[10], p_Wp + OFF_D0U, DINR0, DINP0,  64);
    k_prep_W<<<cdiv(K_ * DINP1 * 128, 256), 256>>>(w[12], p_Wp + OFF_D1G, DINR1, DINP1, 128);
    k_prep_W<<<cdiv(K_ * DINP1 *  64, 256), 256>>>(w[14], p_Wp + OFF_D1U, DINR1, DINP1,  64);

    // encoder layer 0 (din 66 -> padded 80); hout -> g_seq[t]
    for (int t = 0; t < T_; t++) {
        const float* xin   = p_xT + (size_t)t * N_ * B_ * C_;
        const float* hprev = (t == 0) ? nullptr : p_seq + (size_t)(t - 1) * NBH_;
        float* hout        = p_seq + (size_t)t * NBH_;
        run_cell(p_Gt, xin, C_, hprev, hout,
                 p_Wp + OFF_E0G, w[1], p_Wp + OFF_E0U, w[3],
                 p_X0, p_Y0, DINR0, DINP0, /*full=*/t == 0);
    }

    // encoder layer 1 (din 128); x = g_seq[t], state in hB
    for (int t = 0; t < T_; t++) {
        const float* xin   = p_seq + (size_t)t * NBH_;
        const float* hprev = (t == 0) ? nullptr : p_hB;
        run_cell(p_Gt, xin, H_, hprev, p_hB,
                 p_Wp + OFF_E1G, w[5], p_Wp + OFF_E1U, w[7],
                 p_X1, p_Y1, DINR1, DINP1, /*full=*/t == 0);
    }

    // decoder feedback init (y = 0). Xp0 h-cols hold enc0(T-1) h' (fused write,
    // untouched by enc1); Xp1 h-cols hold enc1(T-1) h'.
    cudaMemsetAsync(p_y, 0, (size_t)M_ * C_ * sizeof(float));

    // decoder loop
    for (int t = 0; t < HOR_; t++) {
        const float* h0prev = (t == 0) ? (p_seq + (size_t)(T_ - 1) * NBH_)
                                       : p_hA;
        run_cell(p_Gt, p_y, C_, h0prev, p_hA,
                 p_Wp + OFF_D0G, w[9], p_Wp + OFF_D0U, w[11],
                 p_X0, p_Y0, DINR0, DINP0, /*full=*/false);
        run_cell(p_Gt, p_hA, H_, p_hB, p_hB,
                 p_Wp + OFF_D1G, w[13], p_Wp + OFF_D1U, w[15],
                 p_X1, p_Y1, DINR1, DINP1, /*full=*/false);
        k_proj<<<cdiv(M_, 256), 256>>>(projW, projb, t, out);
    }
}

// round 13
// speedup vs baseline: 1.2001x; 1.1094x over previous
#include <cuda_runtime.h>
#include <cuda_fp16.h>
#include <math.h>
#include <stdint.h>

// ---------------------------------------------------------------------------
// GCGRU encoder-decoder. FP16 legacy tensor cores (mma.m16n8k16, fp32 accum),
// ldmatrix loads, 2-stage cp.async (R10 GEMM config), fused concat epilogues
// (R12), and R13: cross-layer Y reuse — layer-0 gate h-column products
// G[s]@h' are copied from the layer-1 gate's x-column products instead of
// being recomputed (bit-identical; saves ~18% of stage-1 FLOPs).
//
// Layouts (all half):
//   g_X*  : (N, din_p, B)        stage-1 input, pad cols zero
//   g_Y*  : (slot, N, din_p, B)  stage-1 output for supports {1,2,4,5};
//                                identity supports (0,3) read from g_X.
//   g_Gt  : (slot, N, N)         4 non-identity supports
//   g_Wp  : padded (K*din_p, outd) weights
// ---------------------------------------------------------------------------

#define N_    1024
#define B_    64
#define T_    12
#define HOR_  12
#define C_    2
#define H_    64
#define K_    6

#define NBH_  (N_ * B_ * H_)
#define M_    (N_ * B_)

#define DINR0 66
#define DINP0 80
#define DINR1 128
#define DINP1 128
#define LDP0  (DINP0 * B_)   // 5120
#define LDP1  (DINP1 * B_)   // 8192

// ------------------------- scratch (device globals) -------------------------
__device__ float  g_xT[T_ * N_ * B_ * C_];
__device__ float  g_seq[T_ * N_ * B_ * H_];
__device__ float  g_hA[NBH_];
__device__ float  g_hB[NBH_];
__device__ __half g_X0[N_ * LDP0];
__device__ __half g_X1[N_ * LDP1];
__device__ __half g_Y0[4ll * N_ * LDP0];
__device__ __half g_Y1[4ll * N_ * LDP1];
__device__ float  g_zr[(size_t)M_ * 2 * H_];
__device__ float  g_y[M_ * C_];
__device__ __half g_Gt[4 * N_ * N_];
__device__ __half g_Wp[479232];

// ------------------------------ helpers -------------------------------------
__device__ __forceinline__ void mma_f16(float* c, const uint32_t* a,
                                        const uint32_t* b) {
    asm volatile(
        "mma.sync.aligned.m16n8k16.row.col.f32.f16.f16.f32 "
        "{%0,%1,%2,%3}, {%4,%5,%6,%7}, {%8,%9}, {%0,%1,%2,%3};\n"
        : "+f"(c[0]), "+f"(c[1]), "+f"(c[2]), "+f"(c[3])
        : "r"(a[0]), "r"(a[1]), "r"(a[2]), "r"(a[3]), "r"(b[0]), "r"(b[1]));
}

__device__ __forceinline__ void ldmx4(uint32_t* r, const void* p) {
    uint32_t a = (uint32_t)__cvta_generic_to_shared(p);
    asm volatile("ldmatrix.sync.aligned.m8n8.x4.shared.b16 {%0,%1,%2,%3}, [%4];"
                 : "=r"(r[0]), "=r"(r[1]), "=r"(r[2]), "=r"(r[3]) : "r"(a));
}
__device__ __forceinline__ void ldmx4t(uint32_t* r, const void* p) {
    uint32_t a = (uint32_t)__cvta_generic_to_shared(p);
    asm volatile("ldmatrix.sync.aligned.m8n8.x4.trans.shared.b16 {%0,%1,%2,%3}, [%4];"
                 : "=r"(r[0]), "=r"(r[1]), "=r"(r[2]), "=r"(r[3]) : "r"(a));
}

__device__ __forceinline__ void cp16(void* dst, const void* src) {
    uint32_t d = (uint32_t)__cvta_generic_to_shared(dst);
    asm volatile("cp.async.ca.shared.global [%0], [%1], 16;\n"
                 :: "r"(d), "l"(src));
}
__device__ __forceinline__ void cp16cg(void* dst, const void* src) {
    uint32_t d = (uint32_t)__cvta_generic_to_shared(dst);
    asm volatile("cp.async.cg.shared.global [%0], [%1], 16;\n"
                 :: "r"(d), "l"(src));
}
__device__ __forceinline__ void cp_commit() {
    asm volatile("cp.async.commit_group;\n");
}
template <int n>
__device__ __forceinline__ void cp_wait() {
    asm volatile("cp.async.wait_group %0;\n" :: "n"(n));
}

// ------------------------------ prep kernels --------------------------------

__global__ void k_prep_G(const float* __restrict__ G) {
    int idx = blockIdx.x * blockDim.x + threadIdx.x;
    if (idx >= 4 * N_ * N_) return;
    int s = idx / (N_ * N_);
    int r = idx - s * (N_ * N_);
    int kidx = s + 1 + (s >> 1);   // {1,2,4,5}
    g_Gt[idx] = __float2half_rn(G[(size_t)kidx * N_ * N_ + r]);
}

__global__ void k_prep_W(const float* __restrict__ src, __half* __restrict__ dst,
                         int din_r, int din_p, int outd) {
    int idx = blockIdx.x * blockDim.x + threadIdx.x;
    int total = K_ * din_p * outd;
    if (idx >= total) return;
    int o = idx % outd;
    int row = idx / outd;
    int k = row / din_p;
    int f = row - k * din_p;
    dst[idx] = (f < din_r) ? __float2half_rn(src[(size_t)(k * din_r + f) * outd + o])
                           : __float2half_rn(0.f);
}

// ------------------------------ data movement -------------------------------

// x (B,T,N,C) -> g_xT (T,N,B,C)
__global__ void k_transpose_x(const float* __restrict__ x) {
    int idx = blockIdx.x * blockDim.x + threadIdx.x;
    const int total = B_ * T_ * N_ * C_;
    if (idx >= total) return;
    int c = idx % C_;
    int i = (idx / C_) % N_;
    int t = (idx / (C_ * N_)) % T_;
    int b = idx / (C_ * N_ * T_);
    g_xT[(((size_t)t * N_ + i) * B_ + b) * C_ + c] = x[idx];
}

// Full concat (t=0 cells only): X[i][f][b] = concat(x, h) with h possibly null.
__global__ void k_concat_full(const float* __restrict__ xin, int dinx,
                              const float* __restrict__ h,
                              __half* __restrict__ X, int din_r, int din_p) {
    int idx = blockIdx.x * blockDim.x + threadIdx.x;
    int total = N_ * din_r * B_;
    if (idx >= total) return;
    int b = idx & 63;
    int f = (idx >> 6) % din_r;
    int i = idx / (64 * din_r);
    int m = i * B_ + b;
    float v;
    if (f < dinx) v = xin[(size_t)m * dinx + f];
    else          v = h ? h[(size_t)m * H_ + (f - dinx)] : 0.f;
    X[((size_t)i * din_p + f) * B_ + b] = __float2half_rn(v);
}

// X-columns-only concat (steady state): X[i][f][b] = xin[m][f], f < dinx.
__global__ void k_concat_x(const float* __restrict__ xin, int dinx,
                           __half* __restrict__ X, int din_p) {
    int idx = blockIdx.x * blockDim.x + threadIdx.x;
    int total = N_ * dinx * B_;
    if (idx >= total) return;
    int b = idx & 63;
    int f = (idx >> 6) % dinx;
    int i = idx / (64 * dinx);
    int m = i * B_ + b;
    X[((size_t)i * din_p + f) * B_ + b] =
        __float2half_rn(xin[(size_t)m * dinx + f]);
}

// R13 cross-layer Y reuse: copy layer-1 gate x-column products (G[s]@h'_L0,
// f in [0,64)) into layer-0 Y h-column region (f in [C_, C_+64)).
// uint4 = 8 halves over the b dimension.
__global__ void k_ycopy(const __half* __restrict__ src,
                        __half* __restrict__ dst) {
    int idx = blockIdx.x * blockDim.x + threadIdx.x;   // 4*1024*64*8
    const int total = 4 * N_ * 64 * 8;
    if (idx >= total) return;
    int u = idx & 7;
    int f = (idx >> 3) & 63;
    int i = (idx >> 9) & (N_ - 1);
    int s = idx >> 19;
    size_t so = ((size_t)s * N_ + i) * LDP1 + f * 64 + u * 8;
    size_t dofs = ((size_t)s * N_ + i) * LDP0 + (C_ + f) * 64 + u * 8;
    *(uint4*)&dst[dofs] = *(const uint4*)&src[so];
}

// ------------------------------ stage-1 GEMM --------------------------------
// Y[s] = G[s] @ X over columns [col_off, col_off + gridX*128).
// BM=128, BN=128, BK=64, 8 warps (4x2), warp tile 32x64, fp16 mma m16n8k16.
#define G1_A_ROWS 128
#define G1_A_LD   72
#define G1_B_ROWS 64
#define G1_B_LD   136
#define G1_A_BYTES (G1_A_ROWS * G1_A_LD * 2)
#define G1_B_BYTES (G1_B_ROWS * G1_B_LD * 2)
#define G1_SMEM (2 * (G1_A_BYTES + G1_B_BYTES))   // 71680

__global__ __launch_bounds__(256)
void k_gemm1(const __half* __restrict__ Gt, const __half* __restrict__ X,
             __half* __restrict__ Y, int col_off, int ldp) {
    extern __shared__ __align__(16) char dsm[];
    __half (*As)[G1_A_ROWS][G1_A_LD] =
        reinterpret_cast<__half(*)[G1_A_ROWS][G1_A_LD]>(dsm);
    __half (*Bs)[G1_B_ROWS][G1_B_LD] =
        reinterpret_cast<__half(*)[G1_B_ROWS][G1_B_LD]>(dsm + 2 * G1_A_BYTES);

    const int s = blockIdx.z;
    const __half* A = Gt + (size_t)s * N_ * N_;
    const int m0 = blockIdx.y * 128;
    const int n0 = col_off + blockIdx.x * 128;
    const int tid = threadIdx.x;
    const int lane = tid & 31;
    const int warp = tid >> 5;
    const int wm = (warp & 3) * 32;
    const int wn = (warp >> 2) * 64;
    const int gq = lane >> 2;
    const int t4 = lane & 3;

    float acc[2][8][4];
#pragma unroll
    for (int i = 0; i < 2; i++)
#pragma unroll
        for (int j = 0; j < 8; j++)
#pragma unroll
            for (int l = 0; l < 4; l++) acc[i][j][l] = 0.f;

    auto load_stage = [&](int buf, int kk0) {
#pragma unroll
        for (int i = 0; i < 4; i++) {
            int idx = tid + i * 256;
            int row = idx >> 3;
            int seg = (idx & 7) << 3;
            cp16cg(&As[buf][row][seg], A + (size_t)(m0 + row) * N_ + kk0 + seg);
        }
#pragma unroll
        for (int i = 0; i < 4; i++) {
            int idx = tid + i * 256;
            int r = idx >> 4;
            int seg = (idx & 15) << 3;
            cp16(&Bs[buf][r][seg], X + (size_t)(kk0 + r) * ldp + n0 + seg);
        }
    };

    load_stage(0, 0);
    cp_commit();

    const int KSTEPS = N_ / 64;   // 16
    for (int kt = 0; kt < KSTEPS; kt++) {
        int buf = kt & 1;
        if (kt + 1 < KSTEPS) {
            load_stage(buf ^ 1, (kt + 1) * 64);
            cp_commit();
            cp_wait<1>();
        } else {
            cp_wait<0>();
        }
        __syncthreads();

#pragma unroll
        for (int ks = 0; ks < 4; ks++) {
            const int kb = ks * 16;
            uint32_t a[2][4], b[8][2];
#pragma unroll
            for (int mt = 0; mt < 2; mt++) {
                ldmx4(a[mt], &As[buf][wm + mt * 16 + (lane & 15)]
                                     [kb + (lane >> 4) * 8]);
            }
#pragma unroll
            for (int p = 0; p < 4; p++) {
                uint32_t r[4];
                ldmx4t(r, &Bs[buf][kb + (lane & 7) + ((lane >> 3) & 1) * 8]
                                  [wn + p * 16 + (lane >> 4) * 8]);
                b[2 * p][0] = r[0]; b[2 * p][1] = r[1];
                b[2 * p + 1][0] = r[2]; b[2 * p + 1][1] = r[3];
            }
#pragma unroll
            for (int mt = 0; mt < 2; mt++)
#pragma unroll
                for (int nt = 0; nt < 8; nt++)
                    mma_f16(acc[mt][nt], a[mt], b[nt]);
        }
        __syncthreads();
    }

#pragma unroll
    for (int mt = 0; mt < 2; mt++) {
        int row = m0 + wm + mt * 16 + gq;
#pragma unroll
        for (int nt = 0; nt < 8; nt++) {
            int xcol = n0 + wn + nt * 8 + t4 * 2;
#pragma unroll
            for (int hh = 0; hh < 2; hh++) {
                int rr = row + hh * 8;
                __half2 v = __floats2half2_rn(acc[mt][nt][hh * 2 + 0],
                                              acc[mt][nt][hh * 2 + 1]);
                *(__half2*)&Y[((size_t)s * N_ + rr) * ldp + xcol] = v;
            }
        }
    }
}

// ------------------------- stage-2 gate GEMM (BN=128) ------------------------
// zr = sigmoid(A @ Wg + bg); FUSED: Xh h-cols <- r * hprev.
__global__ __launch_bounds__(256)
void k_gemm2g(const __half* __restrict__ Xp, const __half* __restrict__ Yp,
              const __half* __restrict__ W, const float* __restrict__ bias,
              int din_p, const float* __restrict__ hprev,
              __half* __restrict__ Xh, int dinx) {
    __shared__ __align__(16) __half Ask[2][32][136];
    __shared__ __align__(16) __half Bs[2][32][136];

    const int m0 = blockIdx.y * 128;
    const int i0 = m0 >> 6;
    const int tid = threadIdx.x;
    const int lane = tid & 31;
    const int warp = tid >> 5;
    const int wm = (warp & 3) * 32;
    const int wn = (warp >> 2) * 64;
    const int gq = lane >> 2;
    const int t4 = lane & 3;
    const int ldp = din_p * B_;

    float acc[2][8][4];
#pragma unroll
    for (int i = 0; i < 2; i++)
#pragma unroll
        for (int j = 0; j < 8; j++)
#pragma unroll
            for (int l = 0; l < 4; l++) acc[i][j][l] = 0.f;

    auto load_stage = [&](int buf, int kt) {
#pragma unroll
        for (int s16 = 0; s16 < 2; s16++) {
            int kk16 = kt * 32 + s16 * 16;
            int k = kk16 / din_p;
            int f0 = kk16 - k * din_p;
            const __half* basep;
            if (k == 0 || k == 3) basep = Xp;
            else basep = Yp + (size_t)((k < 3) ? k - 1 : k - 2) * N_ * ldp;
            int j = tid >> 4;
            int q = tid & 15;
            int node = q >> 3;
            int ch = (q & 7) << 3;
            cp16(&Ask[buf][s16 * 16 + j][node * 64 + ch],
                 basep + ((size_t)(i0 + node) * din_p + f0 + j) * B_ + ch);
        }
        {
            int kk0 = kt * 32;
#pragma unroll
            for (int i = 0; i < 2; i++) {
                int idx = tid + i * 256;
                int r = idx >> 4;
                int ch = (idx & 15) << 3;
                cp16(&Bs[buf][r][ch], W + (size_t)(kk0 + r) * 128 + ch);
            }
        }
    };

    load_stage(0, 0);
    cp_commit();

    const int KSTEPS = (K_ * din_p) >> 5;
    for (int kt = 0; kt < KSTEPS; kt++) {
        int buf = kt & 1;
        if (kt + 1 < KSTEPS) {
            load_stage(buf ^ 1, kt + 1);
            cp_commit();
            cp_wait<1>();
        } else {
            cp_wait<0>();
        }
        __syncthreads();

#pragma unroll
        for (int ks = 0; ks < 2; ks++) {
            const int kb = ks * 16;
            uint32_t a[2][4], b[8][2];
#pragma unroll
            for (int mt = 0; mt < 2; mt++) {
                ldmx4t(a[mt], &Ask[buf][kb + (lane & 7) + ((lane >> 4) & 1) * 8]
                                       [wm + mt * 16 + ((lane >> 3) & 1) * 8]);
            }
#pragma unroll
            for (int p = 0; p < 4; p++) {
                uint32_t r[4];
                ldmx4t(r, &Bs[buf][kb + (lane & 7) + ((lane >> 3) & 1) * 8]
                                  [wn + p * 16 + (lane >> 4) * 8]);
                b[2 * p][0] = r[0]; b[2 * p][1] = r[1];
                b[2 * p + 1][0] = r[2]; b[2 * p + 1][1] = r[3];
            }
#pragma unroll
            for (int mt = 0; mt < 2; mt++)
#pragma unroll
                for (int nt = 0; nt < 8; nt++)
                    mma_f16(acc[mt][nt], a[mt], b[nt]);
        }
        __syncthreads();
    }

#pragma unroll
    for (int mt = 0; mt < 2; mt++) {
        int row = m0 + wm + mt * 16 + gq;
#pragma unroll
        for (int nt = 0; nt < 8; nt++) {
            int nb = wn + nt * 8 + t4 * 2;
#pragma unroll
            for (int hh = 0; hh < 2; hh++) {
                size_t m = (size_t)(row + hh * 8);
#pragma unroll
                for (int cc = 0; cc < 2; cc++) {
                    int n = nb + cc;
                    float v = acc[mt][nt][hh * 2 + cc] + bias[n];
                    float sig = 1.f / (1.f + expf(-v));
                    g_zr[m * (2 * H_) + n] = sig;
                    if (n >= H_) {
                        int j = n - H_;
                        float hv = hprev ? hprev[m * H_ + j] : 0.f;
                        Xh[((size_t)(m >> 6) * din_p + dinx + j) * B_ +
                           (m & 63)] = __float2half_rn(sig * hv);
                    }
                }
            }
        }
    }
}

// ------------------------- stage-2 update GEMM (BN=64) -----------------------
// h' = z*tanh(A @ Wu + bu) + (1-z)*hprev; FUSED: Xh h-cols <- h'.
__global__ __launch_bounds__(256)
void k_gemm2(const __half* __restrict__ Xp, const __half* __restrict__ Yp,
             const __half* __restrict__ W, const float* __restrict__ bias,
             int din_p,
             const float* __restrict__ hprev, float* __restrict__ hout,
             __half* __restrict__ Xh, int dinx) {
    __shared__ __align__(16) __half Ask[2][32][136];
    __shared__ __align__(16) __half Bs[2][32][72];

    const int m0 = blockIdx.y * 128;
    const int i0 = m0 >> 6;
    const int tid = threadIdx.x;
    const int lane = tid & 31;
    const int warp = tid >> 5;
    const int wm = (warp & 3) * 32;
    const int wn = (warp >> 2) * 32;
    const int gq = lane >> 2;
    const int t4 = lane & 3;
    const int ldp = din_p * B_;

    float acc[2][4][4];
#pragma unroll
    for (int i = 0; i < 2; i++)
#pragma unroll
        for (int j = 0; j < 4; j++)
#pragma unroll
            for (int l = 0; l < 4; l++) acc[i][j][l] = 0.f;

    auto load_stage = [&](int buf, int kt) {
#pragma unroll
        for (int s16 = 0; s16 < 2; s16++) {
            int kk16 = kt * 32 + s16 * 16;
            int k = kk16 / din_p;
            int f0 = kk16 - k * din_p;
            const __half* basep;
            if (k == 0 || k == 3) basep = Xp;
            else basep = Yp + (size_t)((k < 3) ? k - 1 : k - 2) * N_ * ldp;
            int j = tid >> 4;
            int q = tid & 15;
            int node = q >> 3;
            int ch = (q & 7) << 3;
            cp16(&Ask[buf][s16 * 16 + j][node * 64 + ch],
                 basep + ((size_t)(i0 + node) * din_p + f0 + j) * B_ + ch);
        }
        {
            int kk0 = kt * 32;
            int r = tid >> 3;
            int ch = (tid & 7) << 3;
            cp16(&Bs[buf][r][ch], W + (size_t)(kk0 + r) * 64 + ch);
        }
    };

    load_stage(0, 0);
    cp_commit();

    const int KSTEPS = (K_ * din_p) >> 5;
    for (int kt = 0; kt < KSTEPS; kt++) {
        int buf = kt & 1;
        if (kt + 1 < KSTEPS) {
            load_stage(buf ^ 1, kt + 1);
            cp_commit();
            cp_wait<1>();
        } else {
            cp_wait<0>();
        }
        __syncthreads();

#pragma unroll
        for (int ks = 0; ks < 2; ks++) {
            const int kb = ks * 16;
            uint32_t a[2][4], b[4][2];
#pragma unroll
            for (int mt = 0; mt < 2; mt++) {
                ldmx4t(a[mt], &Ask[buf][kb + (lane & 7) + ((lane >> 4) & 1) * 8]
                                       [wm + mt * 16 + ((lane >> 3) & 1) * 8]);
            }
#pragma unroll
            for (int p = 0; p < 2; p++) {
                uint32_t r[4];
                ldmx4t(r, &Bs[buf][kb + (lane & 7) + ((lane >> 3) & 1) * 8]
                                  [wn + p * 16 + (lane >> 4) * 8]);
                b[2 * p][0] = r[0]; b[2 * p][1] = r[1];
                b[2 * p + 1][0] = r[2]; b[2 * p + 1][1] = r[3];
            }
#pragma unroll
            for (int mt = 0; mt < 2; mt++)
#pragma unroll
                for (int nt = 0; nt < 4; nt++)
                    mma_f16(acc[mt][nt], a[mt], b[nt]);
        }
        __syncthreads();
    }

#pragma unroll
    for (int mt = 0; mt < 2; mt++) {
        int row = m0 + wm + mt * 16 + gq;
#pragma unroll
        for (int nt = 0; nt < 4; nt++) {
            int nb = wn + nt * 8 + t4 * 2;
#pragma unroll
            for (int hh = 0; hh < 2; hh++) {
                size_t m = (size_t)(row + hh * 8);
#pragma unroll
                for (int cc = 0; cc < 2; cc++) {
                    int n = nb + cc;
                    float v = acc[mt][nt][hh * 2 + cc] + bias[n];
                    float z = g_zr[m * (2 * H_) + n];
                    float hold = hprev ? hprev[m * H_ + n] : 0.f;
                    float hnew = z * tanhf(v) + (1.f - z) * hold;
                    hout[m * H_ + n] = hnew;
                    Xh[((size_t)(m >> 6) * din_p + dinx + n) * B_ + (m & 63)] =
                        __float2half_rn(hnew);
                }
            }
        }
    }
}

// Projection + output scatter + decoder feedback.
__global__ void k_proj(const float* __restrict__ projW,
                       const float* __restrict__ projb,
                       int t, float* __restrict__ out) {
    int m = blockIdx.x * blockDim.x + threadIdx.x;
    if (m >= M_) return;
    int i = m / B_;
    int b = m - i * B_;
    float a0 = projb[0], a1 = projb[1];
    const float* hv = &g_hB[(size_t)m * H_];
#pragma unroll
    for (int j = 0; j < H_; j++) {
        float h = hv[j];
        a0 += h * projW[j * 2 + 0];
        a1 += h * projW[j * 2 + 1];
    }
    g_y[(size_t)m * C_ + 0] = a0;
    g_y[(size_t)m * C_ + 1] = a1;
    size_t o = ((((size_t)b * HOR_ + t) * N_) + i) * C_;
    out[o + 0] = a0;
    out[o + 1] = a1;
}

// ------------------------------ host side -----------------------------------

static inline int cdiv(int a, int b) { return (a + b - 1) / b; }

#define OFF_E0G 0
#define OFF_E0U 61440
#define OFF_D0G 92160
#define OFF_D0U 153600
#define OFF_E1G 184320
#define OFF_E1U 282624
#define OFF_D1G 331776
#define OFF_D1U 430080

// Layer-0 cell (din 66/80). If YpSrc != null, gate h-col Y products are copied
// from the layer-1 buffer (x-region) instead of recomputed; gate gemm1 then
// covers only the x columns (128 cols).
static void run_cell_l0(const __half* Gt, const float* xin,
                        const float* hprev, float* hout,
                        const __half* Wg, const float* bg,
                        const __half* Wu, const float* bu,
                        __half* Xp, __half* Yp, const __half* YpSrc,
                        bool full_concat) {
    if (full_concat) {
        k_concat_full<<<cdiv(N_ * DINR0 * B_, 256), 256>>>(xin, C_, hprev,
                                                           Xp, DINR0, DINP0);
    } else {
        k_concat_x<<<cdiv(N_ * C_ * B_, 256), 256>>>(xin, C_, Xp, DINP0);
    }

    if (YpSrc) {
        k_ycopy<<<cdiv(4 * N_ * 64 * 8, 256), 256>>>(YpSrc, Yp);
        k_gemm1<<<dim3(1, N_ / 128, 4), 256, G1_SMEM>>>(Gt, Xp, Yp, 0, LDP0);
    } else {
        k_gemm1<<<dim3((DINR0 * B_) / 128, N_ / 128, 4), 256, G1_SMEM>>>(
            Gt, Xp, Yp, 0, LDP0);
    }
    k_gemm2g<<<dim3(1, M_ / 128), 256>>>(Xp, Yp, Wg, bg, DINP0, hprev, Xp, C_);

    k_gemm1<<<dim3((H_ * B_) / 128, N_ / 128, 4), 256, G1_SMEM>>>(
        Gt, Xp, Yp, C_ * B_, LDP0);
    k_gemm2<<<dim3(1, M_ / 128), 256>>>(Xp, Yp, Wu, bu, DINP0,
                                        hprev, hout, Xp, C_);
}

// Layer-1 cell (din 128): full gate gemm1 (its x-region is the reuse source).
static void run_cell_l1(const __half* Gt, const float* xin,
                        const float* hprev, float* hout,
                        const __half* Wg, const float* bg,
                        const __half* Wu, const float* bu,
                        __half* Xp, __half* Yp, bool full_concat) {
    if (full_concat) {
        k_concat_full<<<cdiv(N_ * DINR1 * B_, 256), 256>>>(xin, H_, hprev,
                                                           Xp, DINR1, DINP1);
    } else {
        k_concat_x<<<cdiv(N_ * H_ * B_, 256), 256>>>(xin, H_, Xp, DINP1);
    }

    k_gemm1<<<dim3((DINR1 * B_) / 128, N_ / 128, 4), 256, G1_SMEM>>>(
        Gt, Xp, Yp, 0, LDP1);
    k_gemm2g<<<dim3(1, M_ / 128), 256>>>(Xp, Yp, Wg, bg, DINP1, hprev, Xp, H_);

    k_gemm1<<<dim3((H_ * B_) / 128, N_ / 128, 4), 256, G1_SMEM>>>(
        Gt, Xp, Yp, H_ * B_, LDP1);
    k_gemm2<<<dim3(1, M_ / 128), 256>>>(Xp, Yp, Wu, bu, DINP1,
                                        hprev, hout, Xp, H_);
}

extern "C" void kernel_launch(void* const* d_in, const int* in_sizes, int n_in,
                              void* d_out, int out_size) {
    (void)in_sizes; (void)n_in; (void)out_size;

    const float* x = (const float*)d_in[0];
    const float* G = (const float*)d_in[1];
    const float* w[16];
    for (int i = 0; i < 16; i++) w[i] = (const float*)d_in[2 + i];
    const float* projW = (const float*)d_in[18];
    const float* projb = (const float*)d_in[19];
    float* out = (float*)d_out;

    cudaFuncSetAttribute(k_gemm1, cudaFuncAttributeMaxDynamicSharedMemorySize,
                         G1_SMEM);

    float *p_xT, *p_seq, *p_hA, *p_hB, *p_y;
    __half *p_X0, *p_X1, *p_Y0, *p_Y1, *p_Gt, *p_Wp;
    cudaGetSymbolAddress((void**)&p_xT,  g_xT);
    cudaGetSymbolAddress((void**)&p_seq, g_seq);
    cudaGetSymbolAddress((void**)&p_hA,  g_hA);
    cudaGetSymbolAddress((void**)&p_hB,  g_hB);
    cudaGetSymbolAddress((void**)&p_y,   g_y);
    cudaGetSymbolAddress((void**)&p_X0,  g_X0);
    cudaGetSymbolAddress((void**)&p_X1,  g_X1);
    cudaGetSymbolAddress((void**)&p_Y0,  g_Y0);
    cudaGetSymbolAddress((void**)&p_Y1,  g_Y1);
    cudaGetSymbolAddress((void**)&p_Gt,  g_Gt);
    cudaGetSymbolAddress((void**)&p_Wp,  g_Wp);

    // prep
    k_prep_G<<<cdiv(4 * N_ * N_, 256), 256>>>(G);
    {
        int total = B_ * T_ * N_ * C_;
        k_transpose_x<<<cdiv(total, 256), 256>>>(x);
    }
    k_prep_W<<<cdiv(K_ * DINP0 * 128, 256), 256>>>(w[0],  p_Wp + OFF_E0G, DINR0, DINP0, 128);
    k_prep_W<<<cdiv(K_ * DINP0 *  64, 256), 256>>>(w[2],  p_Wp + OFF_E0U, DINR0, DINP0,  64);
    k_prep_W<<<cdiv(K_ * DINP1 * 128, 256), 256>>>(w[4],  p_Wp + OFF_E1G, DINR1, DINP1, 128);
    k_prep_W<<<cdiv(K_ * DINP1 *  64, 256), 256>>>(w[6],  p_Wp + OFF_E1U, DINR1, DINP1,  64);
    k_prep_W<<<cdiv(K_ * DINP0 * 128, 256), 256>>>(w[8],  p_Wp + OFF_D0G, DINR0, DINP0, 128);
    k_prep_W<<<cdiv(K_ * DINP0 *  64, 256), 256>>>(w[10], p_Wp + OFF_D0U, DINR0, DINP0,  64);
    k_prep_W<<<cdiv(K_ * DINP1 * 128, 256), 256>>>(w[12], p_Wp + OFF_D1G, DINR1, DINP1, 128);
    k_prep_W<<<cdiv(K_ * DINP1 *  64, 256), 256>>>(w[14], p_Wp + OFF_D1U, DINR1, DINP1,  64);

    // encoder, interleaved per timestep: enc0(t) then enc1(t).
    // enc0(t>=1) h-col Y products come from enc1(t-1) gate x-region of Yp1.
    for (int t = 0; t < T_; t++) {
        const float* xin0   = p_xT + (size_t)t * N_ * B_ * C_;
        const float* h0prev = (t == 0) ? nullptr : p_seq + (size_t)(t - 1) * NBH_;
        float* h0out        = p_seq + (size_t)t * NBH_;
        run_cell_l0(p_Gt, xin0, h0prev, h0out,
                    p_Wp + OFF_E0G, w[1], p_Wp + OFF_E0U, w[3],
                    p_X0, p_Y0, (t == 0) ? nullptr : p_Y1,
                    /*full=*/t == 0);

        const float* h1prev = (t == 0) ? nullptr : p_hB;
        run_cell_l1(p_Gt, h0out, h1prev, p_hB,
                    p_Wp + OFF_E1G, w[5], p_Wp + OFF_E1U, w[7],
                    p_X1, p_Y1, /*full=*/t == 0);
    }

    // decoder init: y = 0. Xp0/Xp1 h-cols hold last h' (fused writes);
    // Yp1 x-region holds G@h'_enc0(11) (= dec0(0) gate h-col products).
    cudaMemsetAsync(p_y, 0, (size_t)M_ * C_ * sizeof(float));

    for (int t = 0; t < HOR_; t++) {
        const float* h0prev = (t == 0) ? (p_seq + (size_t)(T_ - 1) * NBH_)
                                       : p_hA;
        run_cell_l0(p_Gt, p_y, h0prev, p_hA,
                    p_Wp + OFF_D0G, w[9], p_Wp + OFF_D0U, w[11],
                    p_X0, p_Y0, p_Y1, /*full=*/false);
        run_cell_l1(p_Gt, p_hA, p_hB, p_hB,
                    p_Wp + OFF_D1G, w[13], p_Wp + OFF_D1U, w[15],
                    p_X1, p_Y1, /*full=*/false);
        k_proj<<<cdiv(M_, 256), 256>>>(projW, projb, t, out);
    }
}

// round 14
// speedup vs baseline: 1.2011x; 1.0008x over previous
#include <cuda_runtime.h>
#include <cuda_fp16.h>
#include <math.h>
#include <stdint.h>

// ---------------------------------------------------------------------------
// GCGRU encoder-decoder. FP16 legacy tensor cores (mma.m16n8k16, fp32 accum),
// ldmatrix loads, 2-stage cp.async (R10 GEMM config), fused concat epilogues
// (R12), cross-layer Y reuse (R13).
// R14: k_prep0 merges Y-copy + x-concat (one launch); g_zr stores z only.
//
// Layouts (all half):
//   g_X*  : (N, din_p, B)        stage-1 input, pad cols zero
//   g_Y*  : (slot, N, din_p, B)  stage-1 output for supports {1,2,4,5};
//                                identity supports (0,3) read from g_X.
//   g_Gt  : (slot, N, N)         4 non-identity supports
//   g_Wp  : padded (K*din_p, outd) weights
// ---------------------------------------------------------------------------

#define N_    1024
#define B_    64
#define T_    12
#define HOR_  12
#define C_    2
#define H_    64
#define K_    6

#define NBH_  (N_ * B_ * H_)
#define M_    (N_ * B_)

#define DINR0 66
#define DINP0 80
#define DINR1 128
#define DINP1 128
#define LDP0  (DINP0 * B_)   // 5120
#define LDP1  (DINP1 * B_)   // 8192

// ------------------------- scratch (device globals) -------------------------
__device__ float  g_xT[T_ * N_ * B_ * C_];
__device__ float  g_seq[T_ * N_ * B_ * H_];
__device__ float  g_hA[NBH_];
__device__ float  g_hB[NBH_];
__device__ __half g_X0[N_ * LDP0];
__device__ __half g_X1[N_ * LDP1];
__device__ __half g_Y0[4ll * N_ * LDP0];
__device__ __half g_Y1[4ll * N_ * LDP1];
__device__ float  g_zr[(size_t)M_ * H_];       // z only (r fused into Xp)
__device__ float  g_y[M_ * C_];
__device__ __half g_Gt[4 * N_ * N_];
__device__ __half g_Wp[479232];

// ------------------------------ helpers -------------------------------------
__device__ __forceinline__ void mma_f16(float* c, const uint32_t* a,
                                        const uint32_t* b) {
    asm volatile(
        "mma.sync.aligned.m16n8k16.row.col.f32.f16.f16.f32 "
        "{%0,%1,%2,%3}, {%4,%5,%6,%7}, {%8,%9}, {%0,%1,%2,%3};\n"
        : "+f"(c[0]), "+f"(c[1]), "+f"(c[2]), "+f"(c[3])
        : "r"(a[0]), "r"(a[1]), "r"(a[2]), "r"(a[3]), "r"(b[0]), "r"(b[1]));
}

__device__ __forceinline__ void ldmx4(uint32_t* r, const void* p) {
    uint32_t a = (uint32_t)__cvta_generic_to_shared(p);
    asm volatile("ldmatrix.sync.aligned.m8n8.x4.shared.b16 {%0,%1,%2,%3}, [%4];"
                 : "=r"(r[0]), "=r"(r[1]), "=r"(r[2]), "=r"(r[3]) : "r"(a));
}
__device__ __forceinline__ void ldmx4t(uint32_t* r, const void* p) {
    uint32_t a = (uint32_t)__cvta_generic_to_shared(p);
    asm volatile("ldmatrix.sync.aligned.m8n8.x4.trans.shared.b16 {%0,%1,%2,%3}, [%4];"
                 : "=r"(r[0]), "=r"(r[1]), "=r"(r[2]), "=r"(r[3]) : "r"(a));
}

__device__ __forceinline__ void cp16(void* dst, const void* src) {
    uint32_t d = (uint32_t)__cvta_generic_to_shared(dst);
    asm volatile("cp.async.ca.shared.global [%0], [%1], 16;\n"
                 :: "r"(d), "l"(src));
}
__device__ __forceinline__ void cp16cg(void* dst, const void* src) {
    uint32_t d = (uint32_t)__cvta_generic_to_shared(dst);
    asm volatile("cp.async.cg.shared.global [%0], [%1], 16;\n"
                 :: "r"(d), "l"(src));
}
__device__ __forceinline__ void cp_commit() {
    asm volatile("cp.async.commit_group;\n");
}
template <int n>
__device__ __forceinline__ void cp_wait() {
    asm volatile("cp.async.wait_group %0;\n" :: "n"(n));
}

// ------------------------------ prep kernels --------------------------------

__global__ void k_prep_G(const float* __restrict__ G) {
    int idx = blockIdx.x * blockDim.x + threadIdx.x;
    if (idx >= 4 * N_ * N_) return;
    int s = idx / (N_ * N_);
    int r = idx - s * (N_ * N_);
    int kidx = s + 1 + (s >> 1);   // {1,2,4,5}
    g_Gt[idx] = __float2half_rn(G[(size_t)kidx * N_ * N_ + r]);
}

__global__ void k_prep_W(const float* __restrict__ src, __half* __restrict__ dst,
                         int din_r, int din_p, int outd) {
    int idx = blockIdx.x * blockDim.x + threadIdx.x;
    int total = K_ * din_p * outd;
    if (idx >= total) return;
    int o = idx % outd;
    int row = idx / outd;
    int k = row / din_p;
    int f = row - k * din_p;
    dst[idx] = (f < din_r) ? __float2half_rn(src[(size_t)(k * din_r + f) * outd + o])
                           : __float2half_rn(0.f);
}

// ------------------------------ data movement -------------------------------

// x (B,T,N,C) -> g_xT (T,N,B,C)
__global__ void k_transpose_x(const float* __restrict__ x) {
    int idx = blockIdx.x * blockDim.x + threadIdx.x;
    const int total = B_ * T_ * N_ * C_;
    if (idx >= total) return;
    int c = idx % C_;
    int i = (idx / C_) % N_;
    int t = (idx / (C_ * N_)) % T_;
    int b = idx / (C_ * N_ * T_);
    g_xT[(((size_t)t * N_ + i) * B_ + b) * C_ + c] = x[idx];
}

// Full concat (t=0 cells only): X[i][f][b] = concat(x, h) with h possibly null.
__global__ void k_concat_full(const float* __restrict__ xin, int dinx,
                              const float* __restrict__ h,
                              __half* __restrict__ X, int din_r, int din_p) {
    int idx = blockIdx.x * blockDim.x + threadIdx.x;
    int total = N_ * din_r * B_;
    if (idx >= total) return;
    int b = idx & 63;
    int f = (idx >> 6) % din_r;
    int i = idx / (64 * din_r);
    int m = i * B_ + b;
    float v;
    if (f < dinx) v = xin[(size_t)m * dinx + f];
    else          v = h ? h[(size_t)m * H_ + (f - dinx)] : 0.f;
    X[((size_t)i * din_p + f) * B_ + b] = __float2half_rn(v);
}

// X-columns-only concat (layer-1 steady state).
__global__ void k_concat_x(const float* __restrict__ xin, int dinx,
                           __half* __restrict__ X, int din_p) {
    int idx = blockIdx.x * blockDim.x + threadIdx.x;
    int total = N_ * dinx * B_;
    if (idx >= total) return;
    int b = idx & 63;
    int f = (idx >> 6) % dinx;
    int i = idx / (64 * dinx);
    int m = i * B_ + b;
    X[((size_t)i * din_p + f) * B_ + b] =
        __float2half_rn(xin[(size_t)m * dinx + f]);
}

// R14: layer-0 steady-state prep (one launch):
//  part 1: Y reuse copy  — layer-1 gate x-col products (f in [0,64)) into
//           layer-0 Y h-col region (f in [C_, C_+64)); uint4 = 8 halves.
//  part 2: x-concat      — X0 x-cols (C_ features) from xin.
#define PREP0_COPYN (4 * N_ * 64 * 8)
#define PREP0_CONCN (N_ * C_ * B_)
__global__ void k_prep0(const __half* __restrict__ src,
                        __half* __restrict__ dst,
                        const float* __restrict__ xin,
                        __half* __restrict__ X) {
    int idx = blockIdx.x * blockDim.x + threadIdx.x;
    if (idx < PREP0_COPYN) {
        int u = idx & 7;
        int f = (idx >> 3) & 63;
        int i = (idx >> 9) & (N_ - 1);
        int s = idx >> 19;
        size_t so = ((size_t)s * N_ + i) * LDP1 + f * 64 + u * 8;
        size_t dofs = ((size_t)s * N_ + i) * LDP0 + (C_ + f) * 64 + u * 8;
        *(uint4*)&dst[dofs] = *(const uint4*)&src[so];
    } else {
        int e = idx - PREP0_COPYN;
        if (e >= PREP0_CONCN) return;
        int b = e & 63;
        int f = (e >> 6) % C_;
        int i = e / (64 * C_);
        int m = i * B_ + b;
        X[((size_t)i * DINP0 + f) * B_ + b] =
            __float2half_rn(xin[(size_t)m * C_ + f]);
    }
}

// ------------------------------ stage-1 GEMM --------------------------------
// Y[s] = G[s] @ X over columns [col_off, col_off + gridX*128).
// BM=128, BN=128, BK=64, 8 warps (4x2), warp tile 32x64, fp16 mma m16n8k16.
#define G1_A_ROWS 128
#define G1_A_LD   72
#define G1_B_ROWS 64
#define G1_B_LD   136
#define G1_A_BYTES (G1_A_ROWS * G1_A_LD * 2)
#define G1_B_BYTES (G1_B_ROWS * G1_B_LD * 2)
#define G1_SMEM (2 * (G1_A_BYTES + G1_B_BYTES))   // 71680

__global__ __launch_bounds__(256)
void k_gemm1(const __half* __restrict__ Gt, const __half* __restrict__ X,
             __half* __restrict__ Y, int col_off, int ldp) {
    extern __shared__ __align__(16) char dsm[];
    __half (*As)[G1_A_ROWS][G1_A_LD] =
        reinterpret_cast<__half(*)[G1_A_ROWS][G1_A_LD]>(dsm);
    __half (*Bs)[G1_B_ROWS][G1_B_LD] =
        reinterpret_cast<__half(*)[G1_B_ROWS][G1_B_LD]>(dsm + 2 * G1_A_BYTES);

    const int s = blockIdx.z;
    const __half* A = Gt + (size_t)s * N_ * N_;
    const int m0 = blockIdx.y * 128;
    const int n0 = col_off + blockIdx.x * 128;
    const int tid = threadIdx.x;
    const int lane = tid & 31;
    const int warp = tid >> 5;
    const int wm = (warp & 3) * 32;
    const int wn = (warp >> 2) * 64;
    const int gq = lane >> 2;
    const int t4 = lane & 3;

    float acc[2][8][4];
#pragma unroll
    for (int i = 0; i < 2; i++)
#pragma unroll
        for (int j = 0; j < 8; j++)
#pragma unroll
            for (int l = 0; l < 4; l++) acc[i][j][l] = 0.f;

    auto load_stage = [&](int buf, int kk0) {
#pragma unroll
        for (int i = 0; i < 4; i++) {
            int idx = tid + i * 256;
            int row = idx >> 3;
            int seg = (idx & 7) << 3;
            cp16cg(&As[buf][row][seg], A + (size_t)(m0 + row) * N_ + kk0 + seg);
        }
#pragma unroll
        for (int i = 0; i < 4; i++) {
            int idx = tid + i * 256;
            int r = idx >> 4;
            int seg = (idx & 15) << 3;
            cp16(&Bs[buf][r][seg], X + (size_t)(kk0 + r) * ldp + n0 + seg);
        }
    };

    load_stage(0, 0);
    cp_commit();

    const int KSTEPS = N_ / 64;   // 16
    for (int kt = 0; kt < KSTEPS; kt++) {
        int buf = kt & 1;
        if (kt + 1 < KSTEPS) {
            load_stage(buf ^ 1, (kt + 1) * 64);
            cp_commit();
            cp_wait<1>();
        } else {
            cp_wait<0>();
        }
        __syncthreads();

#pragma unroll
        for (int ks = 0; ks < 4; ks++) {
            const int kb = ks * 16;
            uint32_t a[2][4], b[8][2];
#pragma unroll
            for (int mt = 0; mt < 2; mt++) {
                ldmx4(a[mt], &As[buf][wm + mt * 16 + (lane & 15)]
                                     [kb + (lane >> 4) * 8]);
            }
#pragma unroll
            for (int p = 0; p < 4; p++) {
                uint32_t r[4];
                ldmx4t(r, &Bs[buf][kb + (lane & 7) + ((lane >> 3) & 1) * 8]
                                  [wn + p * 16 + (lane >> 4) * 8]);
                b[2 * p][0] = r[0]; b[2 * p][1] = r[1];
                b[2 * p + 1][0] = r[2]; b[2 * p + 1][1] = r[3];
            }
#pragma unroll
            for (int mt = 0; mt < 2; mt++)
#pragma unroll
                for (int nt = 0; nt < 8; nt++)
                    mma_f16(acc[mt][nt], a[mt], b[nt]);
        }
        __syncthreads();
    }

#pragma unroll
    for (int mt = 0; mt < 2; mt++) {
        int row = m0 + wm + mt * 16 + gq;
#pragma unroll
        for (int nt = 0; nt < 8; nt++) {
            int xcol = n0 + wn + nt * 8 + t4 * 2;
#pragma unroll
            for (int hh = 0; hh < 2; hh++) {
                int rr = row + hh * 8;
                __half2 v = __floats2half2_rn(acc[mt][nt][hh * 2 + 0],
                                              acc[mt][nt][hh * 2 + 1]);
                *(__half2*)&Y[((size_t)s * N_ + rr) * ldp + xcol] = v;
            }
        }
    }
}

// ------------------------- stage-2 gate GEMM (BN=128) ------------------------
// z-half -> g_zr (fp32, z only); FUSED: Xh h-cols <- r * hprev (half).
__global__ __launch_bounds__(256)
void k_gemm2g(const __half* __restrict__ Xp, const __half* __restrict__ Yp,
              const __half* __restrict__ W, const float* __restrict__ bias,
              int din_p, const float* __restrict__ hprev,
              __half* __restrict__ Xh, int dinx) {
    __shared__ __align__(16) __half Ask[2][32][136];
    __shared__ __align__(16) __half Bs[2][32][136];

    const int m0 = blockIdx.y * 128;
    const int i0 = m0 >> 6;
    const int tid = threadIdx.x;
    const int lane = tid & 31;
    const int warp = tid >> 5;
    const int wm = (warp & 3) * 32;
    const int wn = (warp >> 2) * 64;
    const int gq = lane >> 2;
    const int t4 = lane & 3;
    const int ldp = din_p * B_;

    float acc[2][8][4];
#pragma unroll
    for (int i = 0; i < 2; i++)
#pragma unroll
        for (int j = 0; j < 8; j++)
#pragma unroll
            for (int l = 0; l < 4; l++) acc[i][j][l] = 0.f;

    auto load_stage = [&](int buf, int kt) {
#pragma unroll
        for (int s16 = 0; s16 < 2; s16++) {
            int kk16 = kt * 32 + s16 * 16;
            int k = kk16 / din_p;
            int f0 = kk16 - k * din_p;
            const __half* basep;
            if (k == 0 || k == 3) basep = Xp;
            else basep = Yp + (size_t)((k < 3) ? k - 1 : k - 2) * N_ * ldp;
            int j = tid >> 4;
            int q = tid & 15;
            int node = q >> 3;
            int ch = (q & 7) << 3;
            cp16(&Ask[buf][s16 * 16 + j][node * 64 + ch],
                 basep + ((size_t)(i0 + node) * din_p + f0 + j) * B_ + ch);
        }
        {
            int kk0 = kt * 32;
#pragma unroll
            for (int i = 0; i < 2; i++) {
                int idx = tid + i * 256;
                int r = idx >> 4;
                int ch = (idx & 15) << 3;
                cp16(&Bs[buf][r][ch], W + (size_t)(kk0 + r) * 128 + ch);
            }
        }
    };

    load_stage(0, 0);
    cp_commit();

    const int KSTEPS = (K_ * din_p) >> 5;
    for (int kt = 0; kt < KSTEPS; kt++) {
        int buf = kt & 1;
        if (kt + 1 < KSTEPS) {
            load_stage(buf ^ 1, kt + 1);
            cp_commit();
            cp_wait<1>();
        } else {
            cp_wait<0>();
        }
        __syncthreads();

#pragma unroll
        for (int ks = 0; ks < 2; ks++) {
            const int kb = ks * 16;
            uint32_t a[2][4], b[8][2];
#pragma unroll
            for (int mt = 0; mt < 2; mt++) {
                ldmx4t(a[mt], &Ask[buf][kb + (lane & 7) + ((lane >> 4) & 1) * 8]
                                       [wm + mt * 16 + ((lane >> 3) & 1) * 8]);
            }
#pragma unroll
            for (int p = 0; p < 4; p++) {
                uint32_t r[4];
                ldmx4t(r, &Bs[buf][kb + (lane & 7) + ((lane >> 3) & 1) * 8]
                                  [wn + p * 16 + (lane >> 4) * 8]);
                b[2 * p][0] = r[0]; b[2 * p][1] = r[1];
                b[2 * p + 1][0] = r[2]; b[2 * p + 1][1] = r[3];
            }
#pragma unroll
            for (int mt = 0; mt < 2; mt++)
#pragma unroll
                for (int nt = 0; nt < 8; nt++)
                    mma_f16(acc[mt][nt], a[mt], b[nt]);
        }
        __syncthreads();
    }

#pragma unroll
    for (int mt = 0; mt < 2; mt++) {
        int row = m0 + wm + mt * 16 + gq;
#pragma unroll
        for (int nt = 0; nt < 8; nt++) {
            int nb = wn + nt * 8 + t4 * 2;
#pragma unroll
            for (int hh = 0; hh < 2; hh++) {
                size_t m = (size_t)(row + hh * 8);
#pragma unroll
                for (int cc = 0; cc < 2; cc++) {
                    int n = nb + cc;
                    float v = acc[mt][nt][hh * 2 + cc] + bias[n];
                    float sig = 1.f / (1.f + expf(-v));
                    if (n < H_) {
                        g_zr[m * H_ + n] = sig;          // z
                    } else {
                        int j = n - H_;                  // r -> fused r*h
                        float hv = hprev ? hprev[m * H_ + j] : 0.f;
                        Xh[((size_t)(m >> 6) * din_p + dinx + j) * B_ +
                           (m & 63)] = __float2half_rn(sig * hv);
                    }
                }
            }
        }
    }
}

// ------------------------- stage-2 update GEMM (BN=64) -----------------------
// h' = z*tanh(A @ Wu + bu) + (1-z)*hprev; FUSED: Xh h-cols <- h'.
__global__ __launch_bounds__(256)
void k_gemm2(const __half* __restrict__ Xp, const __half* __restrict__ Yp,
             const __half* __restrict__ W, const float* __restrict__ bias,
             int din_p,
             const float* __restrict__ hprev, float* __restrict__ hout,
             __half* __restrict__ Xh, int dinx) {
    __shared__ __align__(16) __half Ask[2][32][136];
    __shared__ __align__(16) __half Bs[2][32][72];

    const int m0 = blockIdx.y * 128;
    const int i0 = m0 >> 6;
    const int tid = threadIdx.x;
    const int lane = tid & 31;
    const int warp = tid >> 5;
    const int wm = (warp & 3) * 32;
    const int wn = (warp >> 2) * 32;
    const int gq = lane >> 2;
    const int t4 = lane & 3;
    const int ldp = din_p * B_;

    float acc[2][4][4];
#pragma unroll
    for (int i = 0; i < 2; i++)
#pragma unroll
        for (int j = 0; j < 4; j++)
#pragma unroll
            for (int l = 0; l < 4; l++) acc[i][j][l] = 0.f;

    auto load_stage = [&](int buf, int kt) {
#pragma unroll
        for (int s16 = 0; s16 < 2; s16++) {
            int kk16 = kt * 32 + s16 * 16;
            int k = kk16 / din_p;
            int f0 = kk16 - k * din_p;
            const __half* basep;
            if (k == 0 || k == 3) basep = Xp;
            else basep = Yp + (size_t)((k < 3) ? k - 1 : k - 2) * N_ * ldp;
            int j = tid >> 4;
            int q = tid & 15;
            int node = q >> 3;
            int ch = (q & 7) << 3;
            cp16(&Ask[buf][s16 * 16 + j][node * 64 + ch],
                 basep + ((size_t)(i0 + node) * din_p + f0 + j) * B_ + ch);
        }
        {
            int kk0 = kt * 32;
            int r = tid >> 3;
            int ch = (tid & 7) << 3;
            cp16(&Bs[buf][r][ch], W + (size_t)(kk0 + r) * 64 + ch);
        }
    };

    load_stage(0, 0);
    cp_commit();

    const int KSTEPS = (K_ * din_p) >> 5;
    for (int kt = 0; kt < KSTEPS; kt++) {
        int buf = kt & 1;
        if (kt + 1 < KSTEPS) {
            load_stage(buf ^ 1, kt + 1);
            cp_commit();
            cp_wait<1>();
        } else {
            cp_wait<0>();
        }
        __syncthreads();

#pragma unroll
        for (int ks = 0; ks < 2; ks++) {
            const int kb = ks * 16;
            uint32_t a[2][4], b[4][2];
#pragma unroll
            for (int mt = 0; mt < 2; mt++) {
                ldmx4t(a[mt], &Ask[buf][kb + (lane & 7) + ((lane >> 4) & 1) * 8]
                                       [wm + mt * 16 + ((lane >> 3) & 1) * 8]);
            }
#pragma unroll
            for (int p = 0; p < 2; p++) {
                uint32_t r[4];
                ldmx4t(r, &Bs[buf][kb + (lane & 7) + ((lane >> 3) & 1) * 8]
                                  [wn + p * 16 + (lane >> 4) * 8]);
                b[2 * p][0] = r[0]; b[2 * p][1] = r[1];
                b[2 * p + 1][0] = r[2]; b[2 * p + 1][1] = r[3];
            }
#pragma unroll
            for (int mt = 0; mt < 2; mt++)
#pragma unroll
                for (int nt = 0; nt < 4; nt++)
                    mma_f16(acc[mt][nt], a[mt], b[nt]);
        }
        __syncthreads();
    }

#pragma unroll
    for (int mt = 0; mt < 2; mt++) {
        int row = m0 + wm + mt * 16 + gq;
#pragma unroll
        for (int nt = 0; nt < 4; nt++) {
            int nb = wn + nt * 8 + t4 * 2;
#pragma unroll
            for (int hh = 0; hh < 2; hh++) {
                size_t m = (size_t)(row + hh * 8);
#pragma unroll
                for (int cc = 0; cc < 2; cc++) {
                    int n = nb + cc;
                    float v = acc[mt][nt][hh * 2 + cc] + bias[n];
                    float z = g_zr[m * H_ + n];
                    float hold = hprev ? hprev[m * H_ + n] : 0.f;
                    float hnew = z * tanhf(v) + (1.f - z) * hold;
                    hout[m * H_ + n] = hnew;
                    Xh[((size_t)(m >> 6) * din_p + dinx + n) * B_ + (m & 63)] =
                        __float2half_rn(hnew);
                }
            }
        }
    }
}

// Projection + output scatter + decoder feedback.
__global__ void k_proj(const float* __restrict__ projW,
                       const float* __restrict__ projb,
                       int t, float* __restrict__ out) {
    int m = blockIdx.x * blockDim.x + threadIdx.x;
    if (m >= M_) return;
    int i = m / B_;
    int b = m - i * B_;
    float a0 = projb[0], a1 = projb[1];
    const float* hv = &g_hB[(size_t)m * H_];
#pragma unroll
    for (int j = 0; j < H_; j++) {
        float h = hv[j];
        a0 += h * projW[j * 2 + 0];
        a1 += h * projW[j * 2 + 1];
    }
    g_y[(size_t)m * C_ + 0] = a0;
    g_y[(size_t)m * C_ + 1] = a1;
    size_t o = ((((size_t)b * HOR_ + t) * N_) + i) * C_;
    out[o + 0] = a0;
    out[o + 1] = a1;
}

// ------------------------------ host side -----------------------------------

static inline int cdiv(int a, int b) { return (a + b - 1) / b; }

#define OFF_E0G 0
#define OFF_E0U 61440
#define OFF_D0G 92160
#define OFF_D0U 153600
#define OFF_E1G 184320
#define OFF_E1U 282624
#define OFF_D1G 331776
#define OFF_D1U 430080

// Layer-0 cell. If YpSrc != null: steady state — one k_prep0 launch does
// Y-copy + x-concat, gate gemm1 covers only the 128 x columns.
static void run_cell_l0(const __half* Gt, const float* xin,
                        const float* hprev, float* hout,
                        const __half* Wg, const float* bg,
                        const __half* Wu, const float* bu,
                        __half* Xp, __half* Yp, const __half* YpSrc,
                        bool full_concat) {
    if (YpSrc) {
        k_prep0<<<cdiv(PREP0_COPYN + PREP0_CONCN, 256), 256>>>(YpSrc, Yp,
                                                               xin, Xp);
        k_gemm1<<<dim3(1, N_ / 128, 4), 256, G1_SMEM>>>(Gt, Xp, Yp, 0, LDP0);
    } else {
        if (full_concat)
            k_concat_full<<<cdiv(N_ * DINR0 * B_, 256), 256>>>(
                xin, C_, hprev, Xp, DINR0, DINP0);
        else
            k_concat_x<<<cdiv(N_ * C_ * B_, 256), 256>>>(xin, C_, Xp, DINP0);
        k_gemm1<<<dim3((DINR0 * B_) / 128, N_ / 128, 4), 256, G1_SMEM>>>(
            Gt, Xp, Yp, 0, LDP0);
    }
    k_gemm2g<<<dim3(1, M_ / 128), 256>>>(Xp, Yp, Wg, bg, DINP0, hprev, Xp, C_);

    k_gemm1<<<dim3((H_ * B_) / 128, N_ / 128, 4), 256, G1_SMEM>>>(
        Gt, Xp, Yp, C_ * B_, LDP0);
    k_gemm2<<<dim3(1, M_ / 128), 256>>>(Xp, Yp, Wu, bu, DINP0,
                                        hprev, hout, Xp, C_);
}

// Layer-1 cell: full gate gemm1 (its x-region is the reuse source).
static void run_cell_l1(const __half* Gt, const float* xin,
                        const float* hprev, float* hout,
                        const __half* Wg, const float* bg,
                        const __half* Wu, const float* bu,
                        __half* Xp, __half* Yp, bool full_concat) {
    if (full_concat) {
        k_concat_full<<<cdiv(N_ * DINR1 * B_, 256), 256>>>(xin, H_, hprev,
                                                           Xp, DINR1, DINP1);
    } else {
        k_concat_x<<<cdiv(N_ * H_ * B_, 256), 256>>>(xin, H_, Xp, DINP1);
    }

    k_gemm1<<<dim3((DINR1 * B_) / 128, N_ / 128, 4), 256, G1_SMEM>>>(
        Gt, Xp, Yp, 0, LDP1);
    k_gemm2g<<<dim3(1, M_ / 128), 256>>>(Xp, Yp, Wg, bg, DINP1, hprev, Xp, H_);

    k_gemm1<<<dim3((H_ * B_) / 128, N_ / 128, 4), 256, G1_SMEM>>>(
        Gt, Xp, Yp, H_ * B_, LDP1);
    k_gemm2<<<dim3(1, M_ / 128), 256>>>(Xp, Yp, Wu, bu, DINP1,
                                        hprev, hout, Xp, H_);
}

extern "C" void kernel_launch(void* const* d_in, const int* in_sizes, int n_in,
                              void* d_out, int out_size) {
    (void)in_sizes; (void)n_in; (void)out_size;

    const float* x = (const float*)d_in[0];
    const float* G = (const float*)d_in[1];
    const float* w[16];
    for (int i = 0; i < 16; i++) w[i] = (const float*)d_in[2 + i];
    const float* projW = (const float*)d_in[18];
    const float* projb = (const float*)d_in[19];
    float* out = (float*)d_out;

    cudaFuncSetAttribute(k_gemm1, cudaFuncAttributeMaxDynamicSharedMemorySize,
                         G1_SMEM);

    float *p_xT, *p_seq, *p_hA, *p_hB, *p_y;
    __half *p_X0, *p_X1, *p_Y0, *p_Y1, *p_Gt, *p_Wp;
    cudaGetSymbolAddress((void**)&p_xT,  g_xT);
    cudaGetSymbolAddress((void**)&p_seq, g_seq);
    cudaGetSymbolAddress((void**)&p_hA,  g_hA);
    cudaGetSymbolAddress((void**)&p_hB,  g_hB);
    cudaGetSymbolAddress((void**)&p_y,   g_y);
    cudaGetSymbolAddress((void**)&p_X0,  g_X0);
    cudaGetSymbolAddress((void**)&p_X1,  g_X1);
    cudaGetSymbolAddress((void**)&p_Y0,  g_Y0);
    cudaGetSymbolAddress((void**)&p_Y1,  g_Y1);
    cudaGetSymbolAddress((void**)&p_Gt,  g_Gt);
    cudaGetSymbolAddress((void**)&p_Wp,  g_Wp);

    // prep
    k_prep_G<<<cdiv(4 * N_ * N_, 256), 256>>>(G);
    {
        int total = B_ * T_ * N_ * C_;
        k_transpose_x<<<cdiv(total, 256), 256>>>(x);
    }
    k_prep_W<<<cdiv(K_ * DINP0 * 128, 256), 256>>>(w[0],  p_Wp + OFF_E0G, DINR0, DINP0, 128);
    k_prep_W<<<cdiv(K_ * DINP0 *  64, 256), 256>>>(w[2],  p_Wp + OFF_E0U, DINR0, DINP0,  64);
    k_prep_W<<<cdiv(K_ * DINP1 * 128, 256), 256>>>(w[4],  p_Wp + OFF_E1G, DINR1, DINP1, 128);
    k_prep_W<<<cdiv(K_ * DINP1 *  64, 256), 256>>>(w[6],  p_Wp + OFF_E1U, DINR1, DINP1,  64);
    k_prep_W<<<cdiv(K_ * DINP0 * 128, 256), 256>>>(w[8],  p_Wp + OFF_D0G, DINR0, DINP0, 128);
    k_prep_W<<<cdiv(K_ * DINP0 *  64, 256), 256>>>(w[10], p_Wp + OFF_D0U, DINR0, DINP0,  64);
    k_prep_W<<<cdiv(K_ * DINP1 * 128, 256), 256>>>(w[12], p_Wp + OFF_D1G, DINR1, DINP1, 128);
    k_prep_W<<<cdiv(K_ * DINP1 *  64, 256), 256>>>(w[14], p_Wp + OFF_D1U, DINR1, DINP1,  64);

    // encoder, interleaved per timestep: enc0(t) then enc1(t).
    for (int t = 0; t < T_; t++) {
        const float* xin0   = p_xT + (size_t)t * N_ * B_ * C_;
        const float* h0prev = (t == 0) ? nullptr : p_seq + (size_t)(t - 1) * NBH_;
        float* h0out        = p_seq + (size_t)t * NBH_;
        run_cell_l0(p_Gt, xin0, h0prev, h0out,
                    p_Wp + OFF_E0G, w[1], p_Wp + OFF_E0U, w[3],
                    p_X0, p_Y0, (t == 0) ? nullptr : p_Y1,
                    /*full=*/t == 0);

        const float* h1prev = (t == 0) ? nullptr : p_hB;
        run_cell_l1(p_Gt, h0out, h1prev, p_hB,
                    p_Wp + OFF_E1G, w[5], p_Wp + OFF_E1U, w[7],
                    p_X1, p_Y1, /*full=*/t == 0);
    }

    // decoder init: y = 0. Xp0/Xp1 h-cols hold last h'; Yp1 x-region holds
    // G@h'_enc0(11) (= dec0(0) gate h-col products).
    cudaMemsetAsync(p_y, 0, (size_t)M_ * C_ * sizeof(float));

    for (int t = 0; t < HOR_; t++) {
        const float* h0prev = (t == 0) ? (p_seq + (size_t)(T_ - 1) * NBH_)
                                       : p_hA;
        run_cell_l0(p_Gt, p_y, h0prev, p_hA,
                    p_Wp + OFF_D0G, w[9], p_Wp + OFF_D0U, w[11],
                    p_X0, p_Y0, p_Y1, /*full=*/false);
        run_cell_l1(p_Gt, p_hA, p_hB, p_hB,
                    p_Wp + OFF_D1G, w[13], p_Wp + OFF_D1U, w[15],
                    p_X1, p_Y1, /*full=*/false);
        k_proj<<<cdiv(M_, 256), 256>>>(projW, projb, t, out);
    }
}

// round 15
// speedup vs baseline: 1.2280x; 1.0224x over previous
#include <cuda_runtime.h>
#include <cuda_fp16.h>
#include <math.h>
#include <stdint.h>

// ---------------------------------------------------------------------------
// GCGRU encoder-decoder. FP16 legacy tensor cores (mma.m16n8k16, fp32 accum),
// ldmatrix loads, 2-stage cp.async GEMMs, fused concat epilogues, cross-layer
// Y reuse. R15: encoder x-products hoisted into one batched GEMM (kills the
// 32-CTA underfilled gate gemm1s); replay-safe memset of zero-h regions.
// ---------------------------------------------------------------------------

#define N_    1024
#define B_    64
#define T_    12
#define HOR_  12
#define C_    2
#define H_    64
#define K_    6

#define NBH_  (N_ * B_ * H_)
#define M_    (N_ * B_)

#define DINR0 66
#define DINP0 80
#define DINR1 128
#define DINP1 128
#define LDP0  (DINP0 * B_)   // 5120
#define LDP1  (DINP1 * B_)   // 8192
#define LDE   (T_ * C_ * B_) // 1536 (encoder x-product ld)

// ------------------------- scratch (device globals) -------------------------
__device__ float  g_xT[T_ * N_ * B_ * C_];
__device__ float  g_seq[T_ * N_ * B_ * H_];
__device__ float  g_hA[NBH_];
__device__ float  g_hB[NBH_];
__device__ __half g_X0[N_ * LDP0];
__device__ __half g_X1[N_ * LDP1];
__device__ __half g_Y0[4ll * N_ * LDP0];
__device__ __half g_Y1[4ll * N_ * LDP1];
__device__ __half g_Xenc[N_ * LDE];
__device__ __half g_Yx0[4ll * N_ * LDE];
__device__ float  g_zr[(size_t)M_ * H_];       // z only
__device__ float  g_y[M_ * C_];
__device__ __half g_Gt[4 * N_ * N_];
__device__ __half g_Wp[479232];

// ------------------------------ helpers -------------------------------------
__device__ __forceinline__ void mma_f16(float* c, const uint32_t* a,
                                        const uint32_t* b) {
    asm volatile(
        "mma.sync.aligned.m16n8k16.row.col.f32.f16.f16.f32 "
        "{%0,%1,%2,%3}, {%4,%5,%6,%7}, {%8,%9}, {%0,%1,%2,%3};\n"
        : "+f"(c[0]), "+f"(c[1]), "+f"(c[2]), "+f"(c[3])
        : "r"(a[0]), "r"(a[1]), "r"(a[2]), "r"(a[3]), "r"(b[0]), "r"(b[1]));
}

__device__ __forceinline__ void ldmx4(uint32_t* r, const void* p) {
    uint32_t a = (uint32_t)__cvta_generic_to_shared(p);
    asm volatile("ldmatrix.sync.aligned.m8n8.x4.shared.b16 {%0,%1,%2,%3}, [%4];"
                 : "=r"(r[0]), "=r"(r[1]), "=r"(r[2]), "=r"(r[3]) : "r"(a));
}
__device__ __forceinline__ void ldmx4t(uint32_t* r, const void* p) {
    uint32_t a = (uint32_t)__cvta_generic_to_shared(p);
    asm volatile("ldmatrix.sync.aligned.m8n8.x4.trans.shared.b16 {%0,%1,%2,%3}, [%4];"
                 : "=r"(r[0]), "=r"(r[1]), "=r"(r[2]), "=r"(r[3]) : "r"(a));
}

__device__ __forceinline__ void cp16(void* dst, const void* src) {
    uint32_t d = (uint32_t)__cvta_generic_to_shared(dst);
    asm volatile("cp.async.ca.shared.global [%0], [%1], 16;\n"
                 :: "r"(d), "l"(src));
}
__device__ __forceinline__ void cp16cg(void* dst, const void* src) {
    uint32_t d = (uint32_t)__cvta_generic_to_shared(dst);
    asm volatile("cp.async.cg.shared.global [%0], [%1], 16;\n"
                 :: "r"(d), "l"(src));
}
__device__ __forceinline__ void cp_commit() {
    asm volatile("cp.async.commit_group;\n");
}
template <int n>
__device__ __forceinline__ void cp_wait() {
    asm volatile("cp.async.wait_group %0;\n" :: "n"(n));
}

// ------------------------------ prep kernels --------------------------------

__global__ void k_prep_G(const float* __restrict__ G) {
    int idx = blockIdx.x * blockDim.x + threadIdx.x;
    if (idx >= 4 * N_ * N_) return;
    int s = idx / (N_ * N_);
    int r = idx - s * (N_ * N_);
    int kidx = s + 1 + (s >> 1);   // {1,2,4,5}
    g_Gt[idx] = __float2half_rn(G[(size_t)kidx * N_ * N_ + r]);
}

__global__ void k_prep_W(const float* __restrict__ src, __half* __restrict__ dst,
                         int din_r, int din_p, int outd) {
    int idx = blockIdx.x * blockDim.x + threadIdx.x;
    int total = K_ * din_p * outd;
    if (idx >= total) return;
    int o = idx % outd;
    int row = idx / outd;
    int k = row / din_p;
    int f = row - k * din_p;
    dst[idx] = (f < din_r) ? __float2half_rn(src[(size_t)(k * din_r + f) * outd + o])
                           : __float2half_rn(0.f);
}

// ------------------------------ data movement -------------------------------

// x (B,T,N,C) -> g_xT (T,N,B,C)
__global__ void k_transpose_x(const float* __restrict__ x) {
    int idx = blockIdx.x * blockDim.x + threadIdx.x;
    const int total = B_ * T_ * N_ * C_;
    if (idx >= total) return;
    int c = idx % C_;
    int i = (idx / C_) % N_;
    int t = (idx / (C_ * N_)) % T_;
    int b = idx / (C_ * N_ * T_);
    g_xT[(((size_t)t * N_ + i) * B_ + b) * C_ + c] = x[idx];
}

// Build Xenc[i][t*128 + f*64 + b] = half(xT[t][i][b][f]) for all t.
__global__ void k_concat_xenc() {
    int idx = blockIdx.x * blockDim.x + threadIdx.x;
    const int total = N_ * T_ * C_ * B_;
    if (idx >= total) return;
    int b = idx & 63;
    int f = (idx >> 6) & 1;          // C_ = 2
    int t = (idx >> 7) % T_;
    int i = idx / (128 * T_);
    float v = g_xT[(((size_t)t * N_ + i) * B_ + b) * C_ + f];
    g_Xenc[(size_t)i * LDE + t * 128 + f * 64 + b] = __float2half_rn(v);
}

// X-columns-only concat (xin layout (m, dinx)).
__global__ void k_concat_x(const float* __restrict__ xin, int dinx,
                           __half* __restrict__ X, int din_p) {
    int idx = blockIdx.x * blockDim.x + threadIdx.x;
    int total = N_ * dinx * B_;
    if (idx >= total) return;
    int b = idx & 63;
    int f = (idx >> 6) % dinx;
    int i = idx / (64 * dinx);
    int m = i * B_ + b;
    X[((size_t)i * din_p + f) * B_ + b] =
        __float2half_rn(xin[(size_t)m * dinx + f]);
}

// Encoder layer-0 prep, one launch, segments ordered so t=0 can launch a
// shorter grid (no h-copy):
//  seg0 xprod copy : Yx0[s][i][t*128+c] -> Yp0[s][i][c]          (65536 uint4)
//  seg1 x-concat   : Xp0 x-cols from xT slice                    (131072)
//  seg2 h-copy     : Yp1 x-region -> Yp0 h-region                (2097152 uint4)
#define P0E_XPRODN (4 * N_ * 16)
#define P0E_XCONCN (N_ * C_ * B_)
#define P0E_HCOPYN (4 * N_ * 64 * 8)
__global__ void k_prep0e(const __half* __restrict__ hsrc,   // Yp1 or unused
                         int t, const float* __restrict__ xin,
                         __half* __restrict__ Yp0, __half* __restrict__ Xp) {
    int idx = blockIdx.x * blockDim.x + threadIdx.x;
    if (idx < P0E_XPRODN) {
        int u = idx & 15;
        int i = (idx >> 4) & (N_ - 1);
        int s = idx >> 14;
        size_t so = ((size_t)s * N_ + i) * LDE + t * 128 + u * 8;
        size_t dofs = ((size_t)s * N_ + i) * LDP0 + u * 8;
        *(uint4*)&Yp0[dofs] = *(const uint4*)&g_Yx0[so];
        return;
    }
    int e = idx - P0E_XPRODN;
    if (e < P0E_XCONCN) {
        int b = e & 63;
        int f = (e >> 6) & 1;
        int i = e >> 7;
        int m = i * B_ + b;
        Xp[((size_t)i * DINP0 + f) * B_ + b] =
            __float2half_rn(xin[(size_t)m * C_ + f]);
        return;
    }
    int e2 = e - P0E_XCONCN;
    if (e2 >= P0E_HCOPYN) return;
    int u = e2 & 7;
    int f = (e2 >> 3) & 63;
    int i = (e2 >> 9) & (N_ - 1);
    int s = e2 >> 19;
    size_t so = ((size_t)s * N_ + i) * LDP1 + f * 64 + u * 8;
    size_t dofs = ((size_t)s * N_ + i) * LDP0 + (C_ + f) * 64 + u * 8;
    *(uint4*)&Yp0[dofs] = *(const uint4*)&hsrc[so];
}

// Decoder layer-0 prep (R14 form): h-copy + x-concat from g_y.
#define PREP0_COPYN (4 * N_ * 64 * 8)
#define PREP0_CONCN (N_ * C_ * B_)
__global__ void k_prep0(const __half* __restrict__ src,
                        __half* __restrict__ dst,
                        const float* __restrict__ xin,
                        __half* __restrict__ X) {
    int idx = blockIdx.x * blockDim.x + threadIdx.x;
    if (idx < PREP0_COPYN) {
        int u = idx & 7;
        int f = (idx >> 3) & 63;
        int i = (idx >> 9) & (N_ - 1);
        int s = idx >> 19;
        size_t so = ((size_t)s * N_ + i) * LDP1 + f * 64 + u * 8;
        size_t dofs = ((size_t)s * N_ + i) * LDP0 + (C_ + f) * 64 + u * 8;
        *(uint4*)&dst[dofs] = *(const uint4*)&src[so];
    } else {
        int e = idx - PREP0_COPYN;
        if (e >= PREP0_CONCN) return;
        int b = e & 63;
        int f = (e >> 6) & 1;
        int i = e >> 7;
        int m = i * B_ + b;
        X[((size_t)i * DINP0 + f) * B_ + b] =
            __float2half_rn(xin[(size_t)m * C_ + f]);
    }
}

// ------------------------------ stage-1 GEMM --------------------------------
// Y[s] = G[s] @ X over columns [col_off, col_off + gridX*128).
// BM=128, BN=128, BK=64, 8 warps (4x2), warp tile 32x64, fp16 mma m16n8k16.
#define G1_A_ROWS 128
#define G1_A_LD   72
#define G1_B_ROWS 64
#define G1_B_LD   136
#define G1_A_BYTES (G1_A_ROWS * G1_A_LD * 2)
#define G1_B_BYTES (G1_B_ROWS * G1_B_LD * 2)
#define G1_SMEM (2 * (G1_A_BYTES + G1_B_BYTES))   // 71680

__global__ __launch_bounds__(256)
void k_gemm1(const __half* __restrict__ Gt, const __half* __restrict__ X,
             __half* __restrict__ Y, int col_off, int ldp) {
    extern __shared__ __align__(16) char dsm[];
    __half (*As)[G1_A_ROWS][G1_A_LD] =
        reinterpret_cast<__half(*)[G1_A_ROWS][G1_A_LD]>(dsm);
    __half (*Bs)[G1_B_ROWS][G1_B_LD] =
        reinterpret_cast<__half(*)[G1_B_ROWS][G1_B_LD]>(dsm + 2 * G1_A_BYTES);

    const int s = blockIdx.z;
    const __half* A = Gt + (size_t)s * N_ * N_;
    const int m0 = blockIdx.y * 128;
    const int n0 = col_off + blockIdx.x * 128;
    const int tid = threadIdx.x;
    const int lane = tid & 31;
    const int warp = tid >> 5;
    const int wm = (warp & 3) * 32;
    const int wn = (warp >> 2) * 64;
    const int gq = lane >> 2;
    const int t4 = lane & 3;

    float acc[2][8][4];
#pragma unroll
    for (int i = 0; i < 2; i++)
#pragma unroll
        for (int j = 0; j < 8; j++)
#pragma unroll
            for (int l = 0; l < 4; l++) acc[i][j][l] = 0.f;

    auto load_stage = [&](int buf, int kk0) {
#pragma unroll
        for (int i = 0; i < 4; i++) {
            int idx = tid + i * 256;
            int row = idx >> 3;
            int seg = (idx & 7) << 3;
            cp16cg(&As[buf][row][seg], A + (size_t)(m0 + row) * N_ + kk0 + seg);
        }
#pragma unroll
        for (int i = 0; i < 4; i++) {
            int idx = tid + i * 256;
            int r = idx >> 4;
            int seg = (idx & 15) << 3;
            cp16(&Bs[buf][r][seg], X + (size_t)(kk0 + r) * ldp + n0 + seg);
        }
    };

    load_stage(0, 0);
    cp_commit();

    const int KSTEPS = N_ / 64;   // 16
    for (int kt = 0; kt < KSTEPS; kt++) {
        int buf = kt & 1;
        if (kt + 1 < KSTEPS) {
            load_stage(buf ^ 1, (kt + 1) * 64);
            cp_commit();
            cp_wait<1>();
        } else {
            cp_wait<0>();
        }
        __syncthreads();

#pragma unroll
        for (int ks = 0; ks < 4; ks++) {
            const int kb = ks * 16;
            uint32_t a[2][4], b[8][2];
#pragma unroll
            for (int mt = 0; mt < 2; mt++) {
                ldmx4(a[mt], &As[buf][wm + mt * 16 + (lane & 15)]
                                     [kb + (lane >> 4) * 8]);
            }
#pragma unroll
            for (int p = 0; p < 4; p++) {
                uint32_t r[4];
                ldmx4t(r, &Bs[buf][kb + (lane & 7) + ((lane >> 3) & 1) * 8]
                                  [wn + p * 16 + (lane >> 4) * 8]);
                b[2 * p][0] = r[0]; b[2 * p][1] = r[1];
                b[2 * p + 1][0] = r[2]; b[2 * p + 1][1] = r[3];
            }
#pragma unroll
            for (int mt = 0; mt < 2; mt++)
#pragma unroll
                for (int nt = 0; nt < 8; nt++)
                    mma_f16(acc[mt][nt], a[mt], b[nt]);
        }
        __syncthreads();
    }

#pragma unroll
    for (int mt = 0; mt < 2; mt++) {
        int row = m0 + wm + mt * 16 + gq;
#pragma unroll
        for (int nt = 0; nt < 8; nt++) {
            int xcol = n0 + wn + nt * 8 + t4 * 2;
#pragma unroll
            for (int hh = 0; hh < 2; hh++) {
                int rr = row + hh * 8;
                __half2 v = __floats2half2_rn(acc[mt][nt][hh * 2 + 0],
                                              acc[mt][nt][hh * 2 + 1]);
                *(__half2*)&Y[((size_t)s * N_ + rr) * ldp + xcol] = v;
            }
        }
    }
}

// ------------------------- stage-2 gate GEMM (BN=128) ------------------------
// z-half -> g_zr; FUSED: Xh h-cols <- r * hprev.
__global__ __launch_bounds__(256)
void k_gemm2g(const __half* __restrict__ Xp, const __half* __restrict__ Yp,
              const __half* __restrict__ W, const float* __restrict__ bias,
              int din_p, const float* __restrict__ hprev,
              __half* __restrict__ Xh, int dinx) {
    __shared__ __align__(16) __half Ask[2][32][136];
    __shared__ __align__(16) __half Bs[2][32][136];

    const int m0 = blockIdx.y * 128;
    const int i0 = m0 >> 6;
    const int tid = threadIdx.x;
    const int lane = tid & 31;
    const int warp = tid >> 5;
    const int wm = (warp & 3) * 32;
    const int wn = (warp >> 2) * 64;
    const int gq = lane >> 2;
    const int t4 = lane & 3;
    const int ldp = din_p * B_;

    float acc[2][8][4];
#pragma unroll
    for (int i = 0; i < 2; i++)
#pragma unroll
        for (int j = 0; j < 8; j++)
#pragma unroll
            for (int l = 0; l < 4; l++) acc[i][j][l] = 0.f;

    auto load_stage = [&](int buf, int kt) {
#pragma unroll
        for (int s16 = 0; s16 < 2; s16++) {
            int kk16 = kt * 32 + s16 * 16;
            int k = kk16 / din_p;
            int f0 = kk16 - k * din_p;
            const __half* basep;
            if (k == 0 || k == 3) basep = Xp;
            else basep = Yp + (size_t)((k < 3) ? k - 1 : k - 2) * N_ * ldp;
            int j = tid >> 4;
            int q = tid & 15;
            int node = q >> 3;
            int ch = (q & 7) << 3;
            cp16(&Ask[buf][s16 * 16 + j][node * 64 + ch],
                 basep + ((size_t)(i0 + node) * din_p + f0 + j) * B_ + ch);
        }
        {
            int kk0 = kt * 32;
#pragma unroll
            for (int i = 0; i < 2; i++) {
                int idx = tid + i * 256;
                int r = idx >> 4;
                int ch = (idx & 15) << 3;
                cp16(&Bs[buf][r][ch], W + (size_t)(kk0 + r) * 128 + ch);
            }
        }
    };

    load_stage(0, 0);
    cp_commit();

    const int KSTEPS = (K_ * din_p) >> 5;
    for (int kt = 0; kt < KSTEPS; kt++) {
        int buf = kt & 1;
        if (kt + 1 < KSTEPS) {
            load_stage(buf ^ 1, kt + 1);
            cp_commit();
            cp_wait<1>();
        } else {
            cp_wait<0>();
        }
        __syncthreads();

#pragma unroll
        for (int ks = 0; ks < 2; ks++) {
            const int kb = ks * 16;
            uint32_t a[2][4], b[8][2];
#pragma unroll
            for (int mt = 0; mt < 2; mt++) {
                ldmx4t(a[mt], &Ask[buf][kb + (lane & 7) + ((lane >> 4) & 1) * 8]
                                       [wm + mt * 16 + ((lane >> 3) & 1) * 8]);
            }
#pragma unroll
            for (int p = 0; p < 4; p++) {
                uint32_t r[4];
                ldmx4t(r, &Bs[buf][kb + (lane & 7) + ((lane >> 3) & 1) * 8]
                                  [wn + p * 16 + (lane >> 4) * 8]);
                b[2 * p][0] = r[0]; b[2 * p][1] = r[1];
                b[2 * p + 1][0] = r[2]; b[2 * p + 1][1] = r[3];
            }
#pragma unroll
            for (int mt = 0; mt < 2; mt++)
#pragma unroll
                for (int nt = 0; nt < 8; nt++)
                    mma_f16(acc[mt][nt], a[mt], b[nt]);
        }
        __syncthreads();
    }

#pragma unroll
    for (int mt = 0; mt < 2; mt++) {
        int row = m0 + wm + mt * 16 + gq;
#pragma unroll
        for (int nt = 0; nt < 8; nt++) {
            int nb = wn + nt * 8 + t4 * 2;
#pragma unroll
            for (int hh = 0; hh < 2; hh++) {
                size_t m = (size_t)(row + hh * 8);
#pragma unroll
                for (int cc = 0; cc < 2; cc++) {
                    int n = nb + cc;
                    float v = acc[mt][nt][hh * 2 + cc] + bias[n];
                    float sig = 1.f / (1.f + expf(-v));
                    if (n < H_) {
                        g_zr[m * H_ + n] = sig;
                    } else {
                        int j = n - H_;
                        float hv = hprev ? hprev[m * H_ + j] : 0.f;
                        Xh[((size_t)(m >> 6) * din_p + dinx + j) * B_ +
                           (m & 63)] = __float2half_rn(sig * hv);
                    }
                }
            }
        }
    }
}

// ------------------------- stage-2 update GEMM (BN=64) -----------------------
// h' = z*tanh(A @ Wu + bu) + (1-z)*hprev; FUSED: Xh h-cols <- h'.
__global__ __launch_bounds__(256)
void k_gemm2(const __half* __restrict__ Xp, const __half* __restrict__ Yp,
             const __half* __restrict__ W, const float* __restrict__ bias,
             int din_p,
             const float* __restrict__ hprev, float* __restrict__ hout,
             __half* __restrict__ Xh, int dinx) {
    __shared__ __align__(16) __half Ask[2][32][136];
    __shared__ __align__(16) __half Bs[2][32][72];

    const int m0 = blockIdx.y * 128;
    const int i0 = m0 >> 6;
    const int tid = threadIdx.x;
    const int lane = tid & 31;
    const int warp = tid >> 5;
    const int wm = (warp & 3) * 32;
    const int wn = (warp >> 2) * 32;
    const int gq = lane >> 2;
    const int t4 = lane & 3;
    const int ldp = din_p * B_;

    float acc[2][4][4];
#pragma unroll
    for (int i = 0; i < 2; i++)
#pragma unroll
        for (int j = 0; j < 4; j++)
#pragma unroll
            for (int l = 0; l < 4; l++) acc[i][j][l] = 0.f;

    auto load_stage = [&](int buf, int kt) {
#pragma unroll
        for (int s16 = 0; s16 < 2; s16++) {
            int kk16 = kt * 32 + s16 * 16;
            int k = kk16 / din_p;
            int f0 = kk16 - k * din_p;
            const __half* basep;
            if (k == 0 || k == 3) basep = Xp;
            else basep = Yp + (size_t)((k < 3) ? k - 1 : k - 2) * N_ * ldp;
            int j = tid >> 4;
            int q = tid & 15;
            int node = q >> 3;
            int ch = (q & 7) << 3;
            cp16(&Ask[buf][s16 * 16 + j][node * 64 + ch],
                 basep + ((size_t)(i0 + node) * din_p + f0 + j) * B_ + ch);
        }
        {
            int kk0 = kt * 32;
            int r = tid >> 3;
            int ch = (tid & 7) << 3;
            cp16(&Bs[buf][r][ch], W + (size_t)(kk0 + r) * 64 + ch);
        }
    };

    load_stage(0, 0);
    cp_commit();

    const int KSTEPS = (K_ * din_p) >> 5;
    for (int kt = 0; kt < KSTEPS; kt++) {
        int buf = kt & 1;
        if (kt + 1 < KSTEPS) {
            load_stage(buf ^ 1, kt + 1);
            cp_commit();
            cp_wait<1>();
        } else {
            cp_wait<0>();
        }
        __syncthreads();

#pragma unroll
        for (int ks = 0; ks < 2; ks++) {
            const int kb = ks * 16;
            uint32_t a[2][4], b[4][2];
#pragma unroll
            for (int mt = 0; mt < 2; mt++) {
                ldmx4t(a[mt], &Ask[buf][kb + (lane & 7) + ((lane >> 4) & 1) * 8]
                                       [wm + mt * 16 + ((lane >> 3) & 1) * 8]);
            }
#pragma unroll
            for (int p = 0; p < 2; p++) {
                uint32_t r[4];
                ldmx4t(r, &Bs[buf][kb + (lane & 7) + ((lane >> 3) & 1) * 8]
                                  [wn + p * 16 + (lane >> 4) * 8]);
                b[2 * p][0] = r[0]; b[2 * p][1] = r[1];
                b[2 * p + 1][0] = r[2]; b[2 * p + 1][1] = r[3];
            }
#pragma unroll
            for (int mt = 0; mt < 2; mt++)
#pragma unroll
                for (int nt = 0; nt < 4; nt++)
                    mma_f16(acc[mt][nt], a[mt], b[nt]);
        }
        __syncthreads();
    }

#pragma unroll
    for (int mt = 0; mt < 2; mt++) {
        int row = m0 + wm + mt * 16 + gq;
#pragma unroll
        for (int nt = 0; nt < 4; nt++) {
            int nb = wn + nt * 8 + t4 * 2;
#pragma unroll
            for (int hh = 0; hh < 2; hh++) {
                size_t m = (size_t)(row + hh * 8);
#pragma unroll
                for (int cc = 0; cc < 2; cc++) {
                    int n = nb + cc;
                    float v = acc[mt][nt][hh * 2 + cc] + bias[n];
                    float z = g_zr[m * H_ + n];
                    float hold = hprev ? hprev[m * H_ + n] : 0.f;
                    float hnew = z * tanhf(v) + (1.f - z) * hold;
                    hout[m * H_ + n] = hnew;
                    Xh[((size_t)(m >> 6) * din_p + dinx + n) * B_ + (m & 63)] =
                        __float2half_rn(hnew);
                }
            }
        }
    }
}

// Projection + output scatter + decoder feedback.
__global__ void k_proj(const float* __restrict__ projW,
                       const float* __restrict__ projb,
                       int t, float* __restrict__ out) {
    int m = blockIdx.x * blockDim.x + threadIdx.x;
    if (m >= M_) return;
    int i = m / B_;
    int b = m - i * B_;
    float a0 = projb[0], a1 = projb[1];
    const float* hv = &g_hB[(size_t)m * H_];
#pragma unroll
    for (int j = 0; j < H_; j++) {
        float h = hv[j];
        a0 += h * projW[j * 2 + 0];
        a1 += h * projW[j * 2 + 1];
    }
    g_y[(size_t)m * C_ + 0] = a0;
    g_y[(size_t)m * C_ + 1] = a1;
    size_t o = ((((size_t)b * HOR_ + t) * N_) + i) * C_;
    out[o + 0] = a0;
    out[o + 1] = a1;
}

// ------------------------------ host side -----------------------------------

static inline int cdiv(int a, int b) { return (a + b - 1) / b; }

#define OFF_E0G 0
#define OFF_E0U 61440
#define OFF_D0G 92160
#define OFF_D0U 153600
#define OFF_E1G 184320
#define OFF_E1U 282624
#define OFF_D1G 331776
#define OFF_D1U 430080

extern "C" void kernel_launch(void* const* d_in, const int* in_sizes, int n_in,
                              void* d_out, int out_size) {
    (void)in_sizes; (void)n_in; (void)out_size;

    const float* x = (const float*)d_in[0];
    const float* G = (const float*)d_in[1];
    const float* w[16];
    for (int i = 0; i < 16; i++) w[i] = (const float*)d_in[2 + i];
    const float* projW = (const float*)d_in[18];
    const float* projb = (const float*)d_in[19];
    float* out = (float*)d_out;

    cudaFuncSetAttribute(k_gemm1, cudaFuncAttributeMaxDynamicSharedMemorySize,
                         G1_SMEM);

    float *p_xT, *p_seq, *p_hA, *p_hB, *p_y;
    __half *p_X0, *p_X1, *p_Y0, *p_Y1, *p_Gt, *p_Wp, *p_Xenc, *p_Yx0;
    cudaGetSymbolAddress((void**)&p_xT,   g_xT);
    cudaGetSymbolAddress((void**)&p_seq,  g_seq);
    cudaGetSymbolAddress((void**)&p_hA,   g_hA);
    cudaGetSymbolAddress((void**)&p_hB,   g_hB);
    cudaGetSymbolAddress((void**)&p_y,    g_y);
    cudaGetSymbolAddress((void**)&p_X0,   g_X0);
    cudaGetSymbolAddress((void**)&p_X1,   g_X1);
    cudaGetSymbolAddress((void**)&p_Y0,   g_Y0);
    cudaGetSymbolAddress((void**)&p_Y1,   g_Y1);
    cudaGetSymbolAddress((void**)&p_Gt,   g_Gt);
    cudaGetSymbolAddress((void**)&p_Wp,   g_Wp);
    cudaGetSymbolAddress((void**)&p_Xenc, g_Xenc);
    cudaGetSymbolAddress((void**)&p_Yx0,  g_Yx0);

    // replay-safe zeroing of all zero-h / pad regions (whole buffers)
    cudaMemsetAsync(p_X0, 0, (size_t)N_ * LDP0 * sizeof(__half));
    cudaMemsetAsync(p_X1, 0, (size_t)N_ * LDP1 * sizeof(__half));
    cudaMemsetAsync(p_Y0, 0, 4ll * N_ * LDP0 * sizeof(__half));
    cudaMemsetAsync(p_Y1, 0, 4ll * N_ * LDP1 * sizeof(__half));
    cudaMemsetAsync(p_y,  0, (size_t)M_ * C_ * sizeof(float));

    // prep
    k_prep_G<<<cdiv(4 * N_ * N_, 256), 256>>>(G);
    k_transpose_x<<<cdiv(B_ * T_ * N_ * C_, 256), 256>>>(x);
    k_prep_W<<<cdiv(K_ * DINP0 * 128, 256), 256>>>(w[0],  p_Wp + OFF_E0G, DINR0, DINP0, 128);
    k_prep_W<<<cdiv(K_ * DINP0 *  64, 256), 256>>>(w[2],  p_Wp + OFF_E0U, DINR0, DINP0,  64);
    k_prep_W<<<cdiv(K_ * DINP1 * 128, 256), 256>>>(w[4],  p_Wp + OFF_E1G, DINR1, DINP1, 128);
    k_prep_W<<<cdiv(K_ * DINP1 *  64, 256), 256>>>(w[6],  p_Wp + OFF_E1U, DINR1, DINP1,  64);
    k_prep_W<<<cdiv(K_ * DINP0 * 128, 256), 256>>>(w[8],  p_Wp + OFF_D0G, DINR0, DINP0, 128);
    k_prep_W<<<cdiv(K_ * DINP0 *  64, 256), 256>>>(w[10], p_Wp + OFF_D0U, DINR0, DINP0,  64);
    k_prep_W<<<cdiv(K_ * DINP1 * 128, 256), 256>>>(w[12], p_Wp + OFF_D1G, DINR1, DINP1, 128);
    k_prep_W<<<cdiv(K_ * DINP1 *  64, 256), 256>>>(w[14], p_Wp + OFF_D1U, DINR1, DINP1,  64);

    // hoisted encoder x-products: one batched, well-filled GEMM
    k_concat_xenc<<<cdiv(N_ * T_ * C_ * B_, 256), 256>>>();
    k_gemm1<<<dim3(LDE / 128, N_ / 128, 4), 256, G1_SMEM>>>(
        p_Gt, p_Xenc, p_Yx0, 0, LDE);

    // ---------------- encoder, interleaved per timestep ----------------
    for (int t = 0; t < T_; t++) {
        const float* xt     = p_xT + (size_t)t * N_ * B_ * C_;
        const float* h0prev = (t == 0) ? nullptr : p_seq + (size_t)(t - 1) * NBH_;
        float* h0out        = p_seq + (size_t)t * NBH_;

        // layer 0: prep (x-prod copy + x-concat [+ h-copy]) — NO gate gemm1
        int p0n = (t == 0) ? (P0E_XPRODN + P0E_XCONCN)
                           : (P0E_XPRODN + P0E_XCONCN + P0E_HCOPYN);
        k_prep0e<<<cdiv(p0n, 256), 256>>>(p_Y1, t, xt, p_Y0, p_X0);
        k_gemm2g<<<dim3(1, M_ / 128), 256>>>(p_X0, p_Y0, p_Wp + OFF_E0G, w[1],
                                             DINP0, h0prev, p_X0, C_);
        k_gemm1<<<dim3((H_ * B_) / 128, N_ / 128, 4), 256, G1_SMEM>>>(
            p_Gt, p_X0, p_Y0, C_ * B_, LDP0);
        k_gemm2<<<dim3(1, M_ / 128), 256>>>(p_X0, p_Y0, p_Wp + OFF_E0U, w[3],
                                            DINP0, h0prev, h0out, p_X0, C_);

        // layer 1
        const float* h1prev = (t == 0) ? nullptr : p_hB;
        k_concat_x<<<cdiv(N_ * H_ * B_, 256), 256>>>(h0out, H_, p_X1, DINP1);
        int gateCols = (t == 0) ? (H_ * B_) : (DINR1 * B_);  // t=0: h zero
        k_gemm1<<<dim3(gateCols / 128, N_ / 128, 4), 256, G1_SMEM>>>(
            p_Gt, p_X1, p_Y1, 0, LDP1);
        k_gemm2g<<<dim3(1, M_ / 128), 256>>>(p_X1, p_Y1, p_Wp + OFF_E1G, w[5],
                                             DINP1, h1prev, p_X1, H_);
        k_gemm1<<<dim3((H_ * B_) / 128, N_ / 128, 4), 256, G1_SMEM>>>(
            p_Gt, p_X1, p_Y1, H_ * B_, LDP1);
        k_gemm2<<<dim3(1, M_ / 128), 256>>>(p_X1, p_Y1, p_Wp + OFF_E1U, w[7],
                                            DINP1, h1prev, p_hB, p_X1, H_);
    }

    // ---------------- decoder ----------------
    for (int t = 0; t < HOR_; t++) {
        const float* h0prev = (t == 0) ? (p_seq + (size_t)(T_ - 1) * NBH_)
                                       : p_hA;

        // layer 0: h-copy + x-concat from y, tiny gate gemm1 over x cols
        k_prep0<<<cdiv(PREP0_COPYN + PREP0_CONCN, 256), 256>>>(p_Y1, p_Y0,
                                                               p_y, p_X0);
        k_gemm1<<<dim3(1, N_ / 128, 4), 256, G1_SMEM>>>(p_Gt, p_X0, p_Y0,
                                                        0, LDP0);
        k_gemm2g<<<dim3(1, M_ / 128), 256>>>(p_X0, p_Y0, p_Wp + OFF_D0G, w[9],
                                             DINP0, h0prev, p_X0, C_);
        k_gemm1<<<dim3((H_ * B_) / 128, N_ / 128, 4), 256, G1_SMEM>>>(
            p_Gt, p_X0, p_Y0, C_ * B_, LDP0);
        k_gemm2<<<dim3(1, M_ / 128), 256>>>(p_X0, p_Y0, p_Wp + OFF_D0U, w[11],
                                            DINP0, h0prev, p_hA, p_X0, C_);

        // layer 1
        k_concat_x<<<cdiv(N_ * H_ * B_, 256), 256>>>(p_hA, H_, p_X1, DINP1);
        k_gemm1<<<dim3((DINR1 * B_) / 128, N_ / 128, 4), 256, G1_SMEM>>>(
            p_Gt, p_X1, p_Y1, 0, LDP1);
        k_gemm2g<<<dim3(1, M_ / 128), 256>>>(p_X1, p_Y1, p_Wp + OFF_D1G, w[13],
                                             DINP1, p_hB, p_X1, H_);
        k_gemm1<<<dim3((H_ * B_) / 128, N_ / 128, 4), 256, G1_SMEM>>>(
            p_Gt, p_X1, p_Y1, H_ * B_, LDP1);
        k_gemm2<<<dim3(1, M_ / 128), 256>>>(p_X1, p_Y1, p_Wp + OFF_D1U, w[15],
                                            DINP1, p_hB, p_hB, p_X1, H_);

        k_proj<<<cdiv(M_, 256), 256>>>(projW, projb, t, out);
    }
}

// round 16
// speedup vs baseline: 1.2741x; 1.0376x over previous
#include <cuda_runtime.h>
#include <cuda_fp16.h>
#include <math.h>
#include <stdint.h>

// ---------------------------------------------------------------------------
// GCGRU encoder-decoder. FP16 legacy tensor cores (mma.m16n8k16, fp32 accum),
// ldmatrix loads, 2-stage cp.async GEMMs, fused concat epilogues, cross-layer
// Y reuse, hoisted encoder x-products (R15).
// R16: update-GEMM epilogue also writes next-layer X1 x-cols (kills all
// k_concat_x launches); dec1 uses k_gemm2p with CTA-local fused projection
// (kills all k_proj launches).
// ---------------------------------------------------------------------------

#define N_    1024
#define B_    64
#define T_    12
#define HOR_  12
#define C_    2
#define H_    64
#define K_    6

#define NBH_  (N_ * B_ * H_)
#define M_    (N_ * B_)

#define DINR0 66
#define DINP0 80
#define DINR1 128
#define DINP1 128
#define LDP0  (DINP0 * B_)   // 5120
#define LDP1  (DINP1 * B_)   // 8192
#define LDE   (T_ * C_ * B_) // 1536

// ------------------------- scratch (device globals) -------------------------
__device__ float  g_xT[T_ * N_ * B_ * C_];
__device__ float  g_seq[T_ * N_ * B_ * H_];
__device__ float  g_hA[NBH_];
__device__ float  g_hB[NBH_];
__device__ __half g_X0[N_ * LDP0];
__device__ __half g_X1[N_ * LDP1];
__device__ __half g_Y0[4ll * N_ * LDP0];
__device__ __half g_Y1[4ll * N_ * LDP1];
__device__ __half g_Xenc[N_ * LDE];
__device__ __half g_Yx0[4ll * N_ * LDE];
__device__ float  g_zr[(size_t)M_ * H_];
__device__ float  g_y[M_ * C_];
__device__ __half g_Gt[4 * N_ * N_];
__device__ __half g_Wp[479232];

// ------------------------------ helpers -------------------------------------
__device__ __forceinline__ void mma_f16(float* c, const uint32_t* a,
                                        const uint32_t* b) {
    asm volatile(
        "mma.sync.aligned.m16n8k16.row.col.f32.f16.f16.f32 "
        "{%0,%1,%2,%3}, {%4,%5,%6,%7}, {%8,%9}, {%0,%1,%2,%3};\n"
        : "+f"(c[0]), "+f"(c[1]), "+f"(c[2]), "+f"(c[3])
        : "r"(a[0]), "r"(a[1]), "r"(a[2]), "r"(a[3]), "r"(b[0]), "r"(b[1]));
}

__device__ __forceinline__ void ldmx4(uint32_t* r, const void* p) {
    uint32_t a = (uint32_t)__cvta_generic_to_shared(p);
    asm volatile("ldmatrix.sync.aligned.m8n8.x4.shared.b16 {%0,%1,%2,%3}, [%4];"
                 : "=r"(r[0]), "=r"(r[1]), "=r"(r[2]), "=r"(r[3]) : "r"(a));
}
__device__ __forceinline__ void ldmx4t(uint32_t* r, const void* p) {
    uint32_t a = (uint32_t)__cvta_generic_to_shared(p);
    asm volatile("ldmatrix.sync.aligned.m8n8.x4.trans.shared.b16 {%0,%1,%2,%3}, [%4];"
                 : "=r"(r[0]), "=r"(r[1]), "=r"(r[2]), "=r"(r[3]) : "r"(a));
}

__device__ __forceinline__ void cp16(void* dst, const void* src) {
    uint32_t d = (uint32_t)__cvta_generic_to_shared(dst);
    asm volatile("cp.async.ca.shared.global [%0], [%1], 16;\n"
                 :: "r"(d), "l"(src));
}
__device__ __forceinline__ void cp16s(uint32_t dst, const void* src) {
    asm volatile("cp.async.ca.shared.global [%0], [%1], 16;\n"
                 :: "r"(dst), "l"(src));
}
__device__ __forceinline__ void cp16cg(void* dst, const void* src) {
    uint32_t d = (uint32_t)__cvta_generic_to_shared(dst);
    asm volatile("cp.async.cg.shared.global [%0], [%1], 16;\n"
                 :: "r"(d), "l"(src));
}
__device__ __forceinline__ void cp_commit() {
    asm volatile("cp.async.commit_group;\n");
}
template <int n>
__device__ __forceinline__ void cp_wait() {
    asm volatile("cp.async.wait_group %0;\n" :: "n"(n));
}

// ------------------------------ prep kernels --------------------------------

__global__ void k_prep_G(const float* __restrict__ G) {
    int idx = blockIdx.x * blockDim.x + threadIdx.x;
    if (idx >= 4 * N_ * N_) return;
    int s = idx / (N_ * N_);
    int r = idx - s * (N_ * N_);
    int kidx = s + 1 + (s >> 1);   // {1,2,4,5}
    g_Gt[idx] = __float2half_rn(G[(size_t)kidx * N_ * N_ + r]);
}

__global__ void k_prep_W(const float* __restrict__ src, __half* __restrict__ dst,
                         int din_r, int din_p, int outd) {
    int idx = blockIdx.x * blockDim.x + threadIdx.x;
    int total = K_ * din_p * outd;
    if (idx >= total) return;
    int o = idx % outd;
    int row = idx / outd;
    int k = row / din_p;
    int f = row - k * din_p;
    dst[idx] = (f < din_r) ? __float2half_rn(src[(size_t)(k * din_r + f) * outd + o])
                           : __float2half_rn(0.f);
}

// ------------------------------ data movement -------------------------------

// x (B,T,N,C) -> g_xT (T,N,B,C)
__global__ void k_transpose_x(const float* __restrict__ x) {
    int idx = blockIdx.x * blockDim.x + threadIdx.x;
    const int total = B_ * T_ * N_ * C_;
    if (idx >= total) return;
    int c = idx % C_;
    int i = (idx / C_) % N_;
    int t = (idx / (C_ * N_)) % T_;
    int b = idx / (C_ * N_ * T_);
    g_xT[(((size_t)t * N_ + i) * B_ + b) * C_ + c] = x[idx];
}

// Build Xenc[i][t*128 + f*64 + b] for all t.
__global__ void k_concat_xenc() {
    int idx = blockIdx.x * blockDim.x + threadIdx.x;
    const int total = N_ * T_ * C_ * B_;
    if (idx >= total) return;
    int b = idx & 63;
    int f = (idx >> 6) & 1;
    int t = (idx >> 7) % T_;
    int i = idx / (128 * T_);
    float v = g_xT[(((size_t)t * N_ + i) * B_ + b) * C_ + f];
    g_Xenc[(size_t)i * LDE + t * 128 + f * 64 + b] = __float2half_rn(v);
}

// Encoder layer-0 prep (R15): xprod copy + x-concat [+ h-copy].
#define P0E_XPRODN (4 * N_ * 16)
#define P0E_XCONCN (N_ * C_ * B_)
#define P0E_HCOPYN (4 * N_ * 64 * 8)
__global__ void k_prep0e(const __half* __restrict__ hsrc,
                         int t, const float* __restrict__ xin,
                         __half* __restrict__ Yp0, __half* __restrict__ Xp) {
    int idx = blockIdx.x * blockDim.x + threadIdx.x;
    if (idx < P0E_XPRODN) {
        int u = idx & 15;
        int i = (idx >> 4) & (N_ - 1);
        int s = idx >> 14;
        size_t so = ((size_t)s * N_ + i) * LDE + t * 128 + u * 8;
        size_t dofs = ((size_t)s * N_ + i) * LDP0 + u * 8;
        *(uint4*)&Yp0[dofs] = *(const uint4*)&g_Yx0[so];
        return;
    }
    int e = idx - P0E_XPRODN;
    if (e < P0E_XCONCN) {
        int b = e & 63;
        int f = (e >> 6) & 1;
        int i = e >> 7;
        int m = i * B_ + b;
        Xp[((size_t)i * DINP0 + f) * B_ + b] =
            __float2half_rn(xin[(size_t)m * C_ + f]);
        return;
    }
    int e2 = e - P0E_XCONCN;
    if (e2 >= P0E_HCOPYN) return;
    int u = e2 & 7;
    int f = (e2 >> 3) & 63;
    int i = (e2 >> 9) & (N_ - 1);
    int s = e2 >> 19;
    size_t so = ((size_t)s * N_ + i) * LDP1 + f * 64 + u * 8;
    size_t dofs = ((size_t)s * N_ + i) * LDP0 + (C_ + f) * 64 + u * 8;
    *(uint4*)&Yp0[dofs] = *(const uint4*)&hsrc[so];
}

// Decoder layer-0 prep: h-copy + x-concat from g_y.
#define PREP0_COPYN (4 * N_ * 64 * 8)
#define PREP0_CONCN (N_ * C_ * B_)
__global__ void k_prep0(const __half* __restrict__ src,
                        __half* __restrict__ dst,
                        const float* __restrict__ xin,
                        __half* __restrict__ X) {
    int idx = blockIdx.x * blockDim.x + threadIdx.x;
    if (idx < PREP0_COPYN) {
        int u = idx & 7;
        int f = (idx >> 3) & 63;
        int i = (idx >> 9) & (N_ - 1);
        int s = idx >> 19;
        size_t so = ((size_t)s * N_ + i) * LDP1 + f * 64 + u * 8;
        size_t dofs = ((size_t)s * N_ + i) * LDP0 + (C_ + f) * 64 + u * 8;
        *(uint4*)&dst[dofs] = *(const uint4*)&src[so];
    } else {
        int e = idx - PREP0_COPYN;
        if (e >= PREP0_CONCN) return;
        int b = e & 63;
        int f = (e >> 6) & 1;
        int i = e >> 7;
        int m = i * B_ + b;
        X[((size_t)i * DINP0 + f) * B_ + b] =
            __float2half_rn(xin[(size_t)m * C_ + f]);
    }
}

// ------------------------------ stage-1 GEMM --------------------------------
#define G1_A_ROWS 128
#define G1_A_LD   72
#define G1_B_ROWS 64
#define G1_B_LD   136
#define G1_A_BYTES (G1_A_ROWS * G1_A_LD * 2)
#define G1_B_BYTES (G1_B_ROWS * G1_B_LD * 2)
#define G1_SMEM (2 * (G1_A_BYTES + G1_B_BYTES))   // 71680

__global__ __launch_bounds__(256)
void k_gemm1(const __half* __restrict__ Gt, const __half* __restrict__ X,
             __half* __restrict__ Y, int col_off, int ldp) {
    extern __shared__ __align__(16) char dsm[];
    __half (*As)[G1_A_ROWS][G1_A_LD] =
        reinterpret_cast<__half(*)[G1_A_ROWS][G1_A_LD]>(dsm);
    __half (*Bs)[G1_B_ROWS][G1_B_LD] =
        reinterpret_cast<__half(*)[G1_B_ROWS][G1_B_LD]>(dsm + 2 * G1_A_BYTES);

    const int s = blockIdx.z;
    const __half* A = Gt + (size_t)s * N_ * N_;
    const int m0 = blockIdx.y * 128;
    const int n0 = col_off + blockIdx.x * 128;
    const int tid = threadIdx.x;
    const int lane = tid & 31;
    const int warp = tid >> 5;
    const int wm = (warp & 3) * 32;
    const int wn = (warp >> 2) * 64;
    const int gq = lane >> 2;
    const int t4 = lane & 3;

    float acc[2][8][4];
#pragma unroll
    for (int i = 0; i < 2; i++)
#pragma unroll
        for (int j = 0; j < 8; j++)
#pragma unroll
            for (int l = 0; l < 4; l++) acc[i][j][l] = 0.f;

    auto load_stage = [&](int buf, int kk0) {
#pragma unroll
        for (int i = 0; i < 4; i++) {
            int idx = tid + i * 256;
            int row = idx >> 3;
            int seg = (idx & 7) << 3;
            cp16cg(&As[buf][row][seg], A + (size_t)(m0 + row) * N_ + kk0 + seg);
        }
#pragma unroll
        for (int i = 0; i < 4; i++) {
            int idx = tid + i * 256;
            int r = idx >> 4;
            int seg = (idx & 15) << 3;
            cp16(&Bs[buf][r][seg], X + (size_t)(kk0 + r) * ldp + n0 + seg);
        }
    };

    load_stage(0, 0);
    cp_commit();

    const int KSTEPS = N_ / 64;
    for (int kt = 0; kt < KSTEPS; kt++) {
        int buf = kt & 1;
        if (kt + 1 < KSTEPS) {
            load_stage(buf ^ 1, (kt + 1) * 64);
            cp_commit();
            cp_wait<1>();
        } else {
            cp_wait<0>();
        }
        __syncthreads();

#pragma unroll
        for (int ks = 0; ks < 4; ks++) {
            const int kb = ks * 16;
            uint32_t a[2][4], b[8][2];
#pragma unroll
            for (int mt = 0; mt < 2; mt++) {
                ldmx4(a[mt], &As[buf][wm + mt * 16 + (lane & 15)]
                                     [kb + (lane >> 4) * 8]);
            }
#pragma unroll
            for (int p = 0; p < 4; p++) {
                uint32_t r[4];
                ldmx4t(r, &Bs[buf][kb + (lane & 7) + ((lane >> 3) & 1) * 8]
                                  [wn + p * 16 + (lane >> 4) * 8]);
                b[2 * p][0] = r[0]; b[2 * p][1] = r[1];
                b[2 * p + 1][0] = r[2]; b[2 * p + 1][1] = r[3];
            }
#pragma unroll
            for (int mt = 0; mt < 2; mt++)
#pragma unroll
                for (int nt = 0; nt < 8; nt++)
                    mma_f16(acc[mt][nt], a[mt], b[nt]);
        }
        __syncthreads();
    }

#pragma unroll
    for (int mt = 0; mt < 2; mt++) {
        int row = m0 + wm + mt * 16 + gq;
#pragma unroll
        for (int nt = 0; nt < 8; nt++) {
            int xcol = n0 + wn + nt * 8 + t4 * 2;
#pragma unroll
            for (int hh = 0; hh < 2; hh++) {
                int rr = row + hh * 8;
                __half2 v = __floats2half2_rn(acc[mt][nt][hh * 2 + 0],
                                              acc[mt][nt][hh * 2 + 1]);
                *(__half2*)&Y[((size_t)s * N_ + rr) * ldp + xcol] = v;
            }
        }
    }
}

// ------------------------- stage-2 gate GEMM (BN=128) ------------------------
__global__ __launch_bounds__(256)
void k_gemm2g(const __half* __restrict__ Xp, const __half* __restrict__ Yp,
              const __half* __restrict__ W, const float* __restrict__ bias,
              int din_p, const float* __restrict__ hprev,
              __half* __restrict__ Xh, int dinx) {
    __shared__ __align__(16) __half Ask[2][32][136];
    __shared__ __align__(16) __half Bs[2][32][136];

    const int m0 = blockIdx.y * 128;
    const int i0 = m0 >> 6;
    const int tid = threadIdx.x;
    const int lane = tid & 31;
    const int warp = tid >> 5;
    const int wm = (warp & 3) * 32;
    const int wn = (warp >> 2) * 64;
    const int gq = lane >> 2;
    const int t4 = lane & 3;
    const int ldp = din_p * B_;

    float acc[2][8][4];
#pragma unroll
    for (int i = 0; i < 2; i++)
#pragma unroll
        for (int j = 0; j < 8; j++)
#pragma unroll
            for (int l = 0; l < 4; l++) acc[i][j][l] = 0.f;

    auto load_stage = [&](int buf, int kt) {
#pragma unroll
        for (int s16 = 0; s16 < 2; s16++) {
            int kk16 = kt * 32 + s16 * 16;
            int k = kk16 / din_p;
            int f0 = kk16 - k * din_p;
            const __half* basep;
            if (k == 0 || k == 3) basep = Xp;
            else basep = Yp + (size_t)((k < 3) ? k - 1 : k - 2) * N_ * ldp;
            int j = tid >> 4;
            int q = tid & 15;
            int node = q >> 3;
            int ch = (q & 7) << 3;
            cp16(&Ask[buf][s16 * 16 + j][node * 64 + ch],
                 basep + ((size_t)(i0 + node) * din_p + f0 + j) * B_ + ch);
        }
        {
            int kk0 = kt * 32;
#pragma unroll
            for (int i = 0; i < 2; i++) {
                int idx = tid + i * 256;
                int r = idx >> 4;
                int ch = (idx & 15) << 3;
                cp16(&Bs[buf][r][ch], W + (size_t)(kk0 + r) * 128 + ch);
            }
        }
    };

    load_stage(0, 0);
    cp_commit();

    const int KSTEPS = (K_ * din_p) >> 5;
    for (int kt = 0; kt < KSTEPS; kt++) {
        int buf = kt & 1;
        if (kt + 1 < KSTEPS) {
            load_stage(buf ^ 1, kt + 1);
            cp_commit();
            cp_wait<1>();
        } else {
            cp_wait<0>();
        }
        __syncthreads();

#pragma unroll
        for (int ks = 0; ks < 2; ks++) {
            const int kb = ks * 16;
            uint32_t a[2][4], b[8][2];
#pragma unroll
            for (int mt = 0; mt < 2; mt++) {
                ldmx4t(a[mt], &Ask[buf][kb + (lane & 7) + ((lane >> 4) & 1) * 8]
                                       [wm + mt * 16 + ((lane >> 3) & 1) * 8]);
            }
#pragma unroll
            for (int p = 0; p < 4; p++) {
                uint32_t r[4];
                ldmx4t(r, &Bs[buf][kb + (lane & 7) + ((lane >> 3) & 1) * 8]
                                  [wn + p * 16 + (lane >> 4) * 8]);
                b[2 * p][0] = r[0]; b[2 * p][1] = r[1];
                b[2 * p + 1][0] = r[2]; b[2 * p + 1][1] = r[3];
            }
#pragma unroll
            for (int mt = 0; mt < 2; mt++)
#pragma unroll
                for (int nt = 0; nt < 8; nt++)
                    mma_f16(acc[mt][nt], a[mt], b[nt]);
        }
        __syncthreads();
    }

#pragma unroll
    for (int mt = 0; mt < 2; mt++) {
        int row = m0 + wm + mt * 16 + gq;
#pragma unroll
        for (int nt = 0; nt < 8; nt++) {
            int nb = wn + nt * 8 + t4 * 2;
#pragma unroll
            for (int hh = 0; hh < 2; hh++) {
                size_t m = (size_t)(row + hh * 8);
#pragma unroll
                for (int cc = 0; cc < 2; cc++) {
                    int n = nb + cc;
                    float v = acc[mt][nt][hh * 2 + cc] + bias[n];
                    float sig = 1.f / (1.f + expf(-v));
                    if (n < H_) {
                        g_zr[m * H_ + n] = sig;
                    } else {
                        int j = n - H_;
                        float hv = hprev ? hprev[m * H_ + j] : 0.f;
                        Xh[((size_t)(m >> 6) * din_p + dinx + j) * B_ +
                           (m & 63)] = __float2half_rn(sig * hv);
                    }
                }
            }
        }
    }
}

// ------------------------- stage-2 update GEMM (BN=64) -----------------------
// h' = z*tanh(.) + (1-z)h; FUSED writes: hout (float), Xh h-cols (own layer),
// optional Xx x-cols (next layer's X1).
__global__ __launch_bounds__(256)
void k_gemm2(const __half* __restrict__ Xp, const __half* __restrict__ Yp,
             const __half* __restrict__ W, const float* __restrict__ bias,
             int din_p,
             const float* __restrict__ hprev, float* __restrict__ hout,
             __half* __restrict__ Xh, int dinx, __half* __restrict__ Xx) {
    __shared__ __align__(16) __half Ask[2][32][136];
    __shared__ __align__(16) __half Bs[2][32][72];

    const int m0 = blockIdx.y * 128;
    const int i0 = m0 >> 6;
    const int tid = threadIdx.x;
    const int lane = tid & 31;
    const int warp = tid >> 5;
    const int wm = (warp & 3) * 32;
    const int wn = (warp >> 2) * 32;
    const int gq = lane >> 2;
    const int t4 = lane & 3;
    const int ldp = din_p * B_;

    float acc[2][4][4];
#pragma unroll
    for (int i = 0; i < 2; i++)
#pragma unroll
        for (int j = 0; j < 4; j++)
#pragma unroll
            for (int l = 0; l < 4; l++) acc[i][j][l] = 0.f;

    auto load_stage = [&](int buf, int kt) {
#pragma unroll
        for (int s16 = 0; s16 < 2; s16++) {
            int kk16 = kt * 32 + s16 * 16;
            int k = kk16 / din_p;
            int f0 = kk16 - k * din_p;
            const __half* basep;
            if (k == 0 || k == 3) basep = Xp;
            else basep = Yp + (size_t)((k < 3) ? k - 1 : k - 2) * N_ * ldp;
            int j = tid >> 4;
            int q = tid & 15;
            int node = q >> 3;
            int ch = (q & 7) << 3;
            cp16(&Ask[buf][s16 * 16 + j][node * 64 + ch],
                 basep + ((size_t)(i0 + node) * din_p + f0 + j) * B_ + ch);
        }
        {
            int kk0 = kt * 32;
            int r = tid >> 3;
            int ch = (tid & 7) << 3;
            cp16(&Bs[buf][r][ch], W + (size_t)(kk0 + r) * 64 + ch);
        }
    };

    load_stage(0, 0);
    cp_commit();

    const int KSTEPS = (K_ * din_p) >> 5;
    for (int kt = 0; kt < KSTEPS; kt++) {
        int buf = kt & 1;
        if (kt + 1 < KSTEPS) {
            load_stage(buf ^ 1, kt + 1);
            cp_commit();
            cp_wait<1>();
        } else {
            cp_wait<0>();
        }
        __syncthreads();

#pragma unroll
        for (int ks = 0; ks < 2; ks++) {
            const int kb = ks * 16;
            uint32_t a[2][4], b[4][2];
#pragma unroll
            for (int mt = 0; mt < 2; mt++) {
                ldmx4t(a[mt], &Ask[buf][kb + (lane & 7) + ((lane >> 4) & 1) * 8]
                                       [wm + mt * 16 + ((lane >> 3) & 1) * 8]);
            }
#pragma unroll
            for (int p = 0; p < 2; p++) {
                uint32_t r[4];
                ldmx4t(r, &Bs[buf][kb + (lane & 7) + ((lane >> 3) & 1) * 8]
                                  [wn + p * 16 + (lane >> 4) * 8]);
                b[2 * p][0] = r[0]; b[2 * p][1] = r[1];
                b[2 * p + 1][0] = r[2]; b[2 * p + 1][1] = r[3];
            }
#pragma unroll
            for (int mt = 0; mt < 2; mt++)
#pragma unroll
                for (int nt = 0; nt < 4; nt++)
                    mma_f16(acc[mt][nt], a[mt], b[nt]);
        }
        __syncthreads();
    }

#pragma unroll
    for (int mt = 0; mt < 2; mt++) {
        int row = m0 + wm + mt * 16 + gq;
#pragma unroll
        for (int nt = 0; nt < 4; nt++) {
            int nb = wn + nt * 8 + t4 * 2;
#pragma unroll
            for (int hh = 0; hh < 2; hh++) {
                size_t m = (size_t)(row + hh * 8);
#pragma unroll
                for (int cc = 0; cc < 2; cc++) {
                    int n = nb + cc;
                    float v = acc[mt][nt][hh * 2 + cc] + bias[n];
                    float z = g_zr[m * H_ + n];
                    float hold = hprev ? hprev[m * H_ + n] : 0.f;
                    float hnew = z * tanhf(v) + (1.f - z) * hold;
                    hout[m * H_ + n] = hnew;
                    __half hh16 = __float2half_rn(hnew);
                    Xh[((size_t)(m >> 6) * din_p + dinx + n) * B_ + (m & 63)] =
                        hh16;
                    if (Xx)
                        Xx[((size_t)(m >> 6) * DINP1 + n) * B_ + (m & 63)] =
                            hh16;
                }
            }
        }
    }
}

// --------------- stage-2 update GEMM + fused projection (dec1) ---------------
// Same as k_gemm2 plus: stage hnew (fp32) in smem, then CTA-local proj
// writes g_y feedback and the output tensor. Dynamic smem.
#define G2P_ASK_B (2 * 32 * 136 * 2)    // 17408
#define G2P_BS_B  (2 * 32 * 72 * 2)     // 9216
#define G2P_HS_B  (128 * 65 * 4)        // 33280
#define G2P_SMEM  (G2P_ASK_B + G2P_BS_B + G2P_HS_B)   // 59904

__global__ __launch_bounds__(256)
void k_gemm2p(const __half* __restrict__ Xp, const __half* __restrict__ Yp,
              const __half* __restrict__ W, const float* __restrict__ bias,
              const float* __restrict__ hprev, float* __restrict__ hout,
              __half* __restrict__ Xh,
              const float* __restrict__ projW, const float* __restrict__ projb,
              int t, float* __restrict__ out) {
    extern __shared__ __align__(16) char dsm2[];
    __half (*Ask)[32][136] = reinterpret_cast<__half(*)[32][136]>(dsm2);
    __half (*Bs)[32][72]   = reinterpret_cast<__half(*)[32][72]>(dsm2 + G2P_ASK_B);
    float (*hs)[65]        = reinterpret_cast<float(*)[65]>(dsm2 + G2P_ASK_B +
                                                            G2P_BS_B);
    const int din_p = DINP1, dinx = H_;
    const int m0 = blockIdx.y * 128;
    const int i0 = m0 >> 6;
    const int tid = threadIdx.x;
    const int lane = tid & 31;
    const int warp = tid >> 5;
    const int wm = (warp & 3) * 32;
    const int wn = (warp >> 2) * 32;
    const int gq = lane >> 2;
    const int t4 = lane & 3;
    const int ldp = din_p * B_;

    float acc[2][4][4];
#pragma unroll
    for (int i = 0; i < 2; i++)
#pragma unroll
        for (int j = 0; j < 4; j++)
#pragma unroll
            for (int l = 0; l < 4; l++) acc[i][j][l] = 0.f;

    auto load_stage = [&](int buf, int kt) {
#pragma unroll
        for (int s16 = 0; s16 < 2; s16++) {
            int kk16 = kt * 32 + s16 * 16;
            int k = kk16 / din_p;
            int f0 = kk16 - k * din_p;
            const __half* basep;
            if (k == 0 || k == 3) basep = Xp;
            else basep = Yp + (size_t)((k < 3) ? k - 1 : k - 2) * N_ * ldp;
            int j = tid >> 4;
            int q = tid & 15;
            int node = q >> 3;
            int ch = (q & 7) << 3;
            cp16(&Ask[buf][s16 * 16 + j][node * 64 + ch],
                 basep + ((size_t)(i0 + node) * din_p + f0 + j) * B_ + ch);
        }
        {
            int kk0 = kt * 32;
            int r = tid >> 3;
            int ch = (tid & 7) << 3;
            cp16(&Bs[buf][r][ch], W + (size_t)(kk0 + r) * 64 + ch);
        }
    };

    load_stage(0, 0);
    cp_commit();

    const int KSTEPS = (K_ * din_p) >> 5;   // 24
    for (int kt = 0; kt < KSTEPS; kt++) {
        int buf = kt & 1;
        if (kt + 1 < KSTEPS) {
            load_stage(buf ^ 1, kt + 1);
            cp_commit();
            cp_wait<1>();
        } else {
            cp_wait<0>();
        }
        __syncthreads();

#pragma unroll
        for (int ks = 0; ks < 2; ks++) {
            const int kb = ks * 16;
            uint32_t a[2][4], b[4][2];
#pragma unroll
            for (int mt = 0; mt < 2; mt++) {
                ldmx4t(a[mt], &Ask[buf][kb + (lane & 7) + ((lane >> 4) & 1) * 8]
                                       [wm + mt * 16 + ((lane >> 3) & 1) * 8]);
            }
#pragma unroll
            for (int p = 0; p < 2; p++) {
                uint32_t r[4];
                ldmx4t(r, &Bs[buf][kb + (lane & 7) + ((lane >> 3) & 1) * 8]
                                  [wn + p * 16 + (lane >> 4) * 8]);
                b[2 * p][0] = r[0]; b[2 * p][1] = r[1];
                b[2 * p + 1][0] = r[2]; b[2 * p + 1][1] = r[3];
            }
#pragma unroll
            for (int mt = 0; mt < 2; mt++)
#pragma unroll
                for (int nt = 0; nt < 4; nt++)
                    mma_f16(acc[mt][nt], a[mt], b[nt]);
        }
        __syncthreads();
    }

#pragma unroll
    for (int mt = 0; mt < 2; mt++) {
        int row = m0 + wm + mt * 16 + gq;
#pragma unroll
        for (int nt = 0; nt < 4; nt++) {
            int nb = wn + nt * 8 + t4 * 2;
#pragma unroll
            for (int hh = 0; hh < 2; hh++) {
                size_t m = (size_t)(row + hh * 8);
#pragma unroll
                for (int cc = 0; cc < 2; cc++) {
                    int n = nb + cc;
                    float v = acc[mt][nt][hh * 2 + cc] + bias[n];
                    float z = g_zr[m * H_ + n];
                    float hold = hprev ? hprev[m * H_ + n] : 0.f;
                    float hnew = z * tanhf(v) + (1.f - z) * hold;
                    hout[m * H_ + n] = hnew;
                    Xh[((size_t)(m >> 6) * din_p + dinx + n) * B_ + (m & 63)] =
                        __float2half_rn(hnew);
                    hs[m - m0][n] = hnew;
                }
            }
        }
    }

    __syncthreads();
    // fused projection: 128 threads, one row each
    if (tid < 128) {
        int m = m0 + tid;
        int i = m >> 6;
        int b = m & 63;
        float a0 = projb[0], a1 = projb[1];
        for (int j = 0; j < H_; j++) {
            float h = hs[tid][j];
            a0 += h * projW[j * 2 + 0];
            a1 += h * projW[j * 2 + 1];
        }
        g_y[(size_t)m * C_ + 0] = a0;
        g_y[(size_t)m * C_ + 1] = a1;
        size_t o = ((((size_t)b * HOR_ + t) * N_) + i) * C_;
        out[o + 0] = a0;
        out[o + 1] = a1;
    }
}

// ------------------------------ host side -----------------------------------

static inline int cdiv(int a, int b) { return (a + b - 1) / b; }

#define OFF_E0G 0
#define OFF_E0U 61440
#define OFF_D0G 92160
#define OFF_D0U 153600
#define OFF_E1G 184320
#define OFF_E1U 282624
#define OFF_D1G 331776
#define OFF_D1U 430080

extern "C" void kernel_launch(void* const* d_in, const int* in_sizes, int n_in,
                              void* d_out, int out_size) {
    (void)in_sizes; (void)n_in; (void)out_size;

    const float* x = (const float*)d_in[0];
    const float* G = (const float*)d_in[1];
    const float* w[16];
    for (int i = 0; i < 16; i++) w[i] = (const float*)d_in[2 + i];
    const float* projW = (const float*)d_in[18];
    const float* projb = (const float*)d_in[19];
    float* out = (float*)d_out;

    cudaFuncSetAttribute(k_gemm1, cudaFuncAttributeMaxDynamicSharedMemorySize,
                         G1_SMEM);
    cudaFuncSetAttribute(k_gemm2p, cudaFuncAttributeMaxDynamicSharedMemorySize,
                         G2P_SMEM);

    float *p_xT, *p_seq, *p_hA, *p_hB, *p_y;
    __half *p_X0, *p_X1, *p_Y0, *p_Y1, *p_Gt, *p_Wp, *p_Xenc, *p_Yx0;
    cudaGetSymbolAddress((void**)&p_xT,   g_xT);
    cudaGetSymbolAddress((void**)&p_seq,  g_seq);
    cudaGetSymbolAddress((void**)&p_hA,   g_hA);
    cudaGetSymbolAddress((void**)&p_hB,   g_hB);
    cudaGetSymbolAddress((void**)&p_y,    g_y);
    cudaGetSymbolAddress((void**)&p_X0,   g_X0);
    cudaGetSymbolAddress((void**)&p_X1,   g_X1);
    cudaGetSymbolAddress((void**)&p_Y0,   g_Y0);
    cudaGetSymbolAddress((void**)&p_Y1,   g_Y1);
    cudaGetSymbolAddress((void**)&p_Gt,   g_Gt);
    cudaGetSymbolAddress((void**)&p_Wp,   g_Wp);
    cudaGetSymbolAddress((void**)&p_Xenc, g_Xenc);
    cudaGetSymbolAddress((void**)&p_Yx0,  g_Yx0);

    // replay-safe zeroing (zero-h regions + pads)
    cudaMemsetAsync(p_X0, 0, (size_t)N_ * LDP0 * sizeof(__half));
    cudaMemsetAsync(p_X1, 0, (size_t)N_ * LDP1 * sizeof(__half));
    cudaMemsetAsync(p_Y0, 0, 4ll * N_ * LDP0 * sizeof(__half));
    cudaMemsetAsync(p_Y1, 0, 4ll * N_ * LDP1 * sizeof(__half));
    cudaMemsetAsync(p_y,  0, (size_t)M_ * C_ * sizeof(float));

    // prep
    k_prep_G<<<cdiv(4 * N_ * N_, 256), 256>>>(G);
    k_transpose_x<<<cdiv(B_ * T_ * N_ * C_, 256), 256>>>(x);
    k_prep_W<<<cdiv(K_ * DINP0 * 128, 256), 256>>>(w[0],  p_Wp + OFF_E0G, DINR0, DINP0, 128);
    k_prep_W<<<cdiv(K_ * DINP0 *  64, 256), 256>>>(w[2],  p_Wp + OFF_E0U, DINR0, DINP0,  64);
    k_prep_W<<<cdiv(K_ * DINP1 * 128, 256), 256>>>(w[4],  p_Wp + OFF_E1G, DINR1, DINP1, 128);
    k_prep_W<<<cdiv(K_ * DINP1 *  64, 256), 256>>>(w[6],  p_Wp + OFF_E1U, DINR1, DINP1,  64);
    k_prep_W<<<cdiv(K_ * DINP0 * 128, 256), 256>>>(w[8],  p_Wp + OFF_D0G, DINR0, DINP0, 128);
    k_prep_W<<<cdiv(K_ * DINP0 *  64, 256), 256>>>(w[10], p_Wp + OFF_D0U, DINR0, DINP0,  64);
    k_prep_W<<<cdiv(K_ * DINP1 * 128, 256), 256>>>(w[12], p_Wp + OFF_D1G, DINR1, DINP1, 128);
    k_prep_W<<<cdiv(K_ * DINP1 *  64, 256), 256>>>(w[14], p_Wp + OFF_D1U, DINR1, DINP1,  64);

    // hoisted encoder x-products
    k_concat_xenc<<<cdiv(N_ * T_ * C_ * B_, 256), 256>>>();
    k_gemm1<<<dim3(LDE / 128, N_ / 128, 4), 256, G1_SMEM>>>(
        p_Gt, p_Xenc, p_Yx0, 0, LDE);

    // ---------------- encoder, interleaved per timestep ----------------
    for (int t = 0; t < T_; t++) {
        const float* xt     = p_xT + (size_t)t * N_ * B_ * C_;
        const float* h0prev = (t == 0) ? nullptr : p_seq + (size_t)(t - 1) * NBH_;
        float* h0out        = p_seq + (size_t)t * NBH_;

        // layer 0 (no gate gemm1; x-prods hoisted; update writes X1 x-cols)
        int p0n = (t == 0) ? (P0E_XPRODN + P0E_XCONCN)
                           : (P0E_XPRODN + P0E_XCONCN + P0E_HCOPYN);
        k_prep0e<<<cdiv(p0n, 256), 256>>>(p_Y1, t, xt, p_Y0, p_X0);
        k_gemm2g<<<dim3(1, M_ / 128), 256>>>(p_X0, p_Y0, p_Wp + OFF_E0G, w[1],
                                             DINP0, h0prev, p_X0, C_);
        k_gemm1<<<dim3((H_ * B_) / 128, N_ / 128, 4), 256, G1_SMEM>>>(
            p_Gt, p_X0, p_Y0, C_ * B_, LDP0);
        k_gemm2<<<dim3(1, M_ / 128), 256>>>(p_X0, p_Y0, p_Wp + OFF_E0U, w[3],
                                            DINP0, h0prev, h0out, p_X0, C_,
                                            p_X1);

        // layer 1
        const float* h1prev = (t == 0) ? nullptr : p_hB;
        int gateCols = (t == 0) ? (H_ * B_) : (DINR1 * B_);
        k_gemm1<<<dim3(gateCols / 128, N_ / 128, 4), 256, G1_SMEM>>>(
            p_Gt, p_X1, p_Y1, 0, LDP1);
        k_gemm2g<<<dim3(1, M_ / 128), 256>>>(p_X1, p_Y1, p_Wp + OFF_E1G, w[5],
                                             DINP1, h1prev, p_X1, H_);
        k_gemm1<<<dim3((H_ * B_) / 128, N_ / 128, 4), 256, G1_SMEM>>>(
            p_Gt, p_X1, p_Y1, H_ * B_, LDP1);
        k_gemm2<<<dim3(1, M_ / 128), 256>>>(p_X1, p_Y1, p_Wp + OFF_E1U, w[7],
                                            DINP1, h1prev, p_hB, p_X1, H_,
                                            nullptr);
    }

    // ---------------- decoder ----------------
    for (int t = 0; t < HOR_; t++) {
        const float* h0prev = (t == 0) ? (p_seq + (size_t)(T_ - 1) * NBH_)
                                       : p_hA;

        // layer 0
        k_prep0<<<cdiv(PREP0_COPYN + PREP0_CONCN, 256), 256>>>(p_Y1, p_Y0,
                                                               p_y, p_X0);
        k_gemm1<<<dim3(1, N_ / 128, 4), 256, G1_SMEM>>>(p_Gt, p_X0, p_Y0,
                                                        0, LDP0);
        k_gemm2g<<<dim3(1, M_ / 128), 256>>>(p_X0, p_Y0, p_Wp + OFF_D0G, w[9],
                                             DINP0, h0prev, p_X0, C_);
        k_gemm1<<<dim3((H_ * B_) / 128, N_ / 128, 4), 256, G1_SMEM>>>(
            p_Gt, p_X0, p_Y0, C_ * B_, LDP0);
        k_gemm2<<<dim3(1, M_ / 128), 256>>>(p_X0, p_Y0, p_Wp + OFF_D0U, w[11],
                                            DINP0, h0prev, p_hA, p_X0, C_,
                                            p_X1);

        // layer 1 (update + fused projection)
        k_gemm1<<<dim3((DINR1 * B_) / 128, N_ / 128, 4), 256, G1_SMEM>>>(
            p_Gt, p_X1, p_Y1, 0, LDP1);
        k_gemm2g<<<dim3(1, M_ / 128), 256>>>(p_X1, p_Y1, p_Wp + OFF_D1G, w[13],
                                             DINP1, p_hB, p_X1, H_);
        k_gemm1<<<dim3((H_ * B_) / 128, N_ / 128, 4), 256, G1_SMEM>>>(
            p_Gt, p_X1, p_Y1, H_ * B_, LDP1);
        k_gemm2p<<<dim3(1, M_ / 128), 256, G2P_SMEM>>>(
            p_X1, p_Y1, p_Wp + OFF_D1U, w[15], p_hB, p_hB, p_X1,
            projW, projb, t, out);
    }
}